// round 1
// baseline (speedup 1.0000x reference)
#include <cuda_runtime.h>
#include <cuda_bf16.h>

// Problem constants
#define BATCH 2
#define SEQ   2048
#define INF   1024
#define HEADS 8
#define DPH   64
#define OUTF  1024
#define NP    512           // HEADS*DPH
#define MROWS (BATCH*SEQ)   // 4096
#define PSZ   (BATCH*SEQ*NP)      // 2097152 floats per projection
#define CTXROWS (BATCH*HEADS*SEQ) // 32768

// Scratch (module-static device memory; no runtime allocation)
__device__ float g_P[3 * PSZ];            // Pq, Pk, Pv  (25 MB)
__device__ float g_ctx[CTXROWS * DPH];    // attention output (8 MB)

// ---------------------------------------------------------------------------
// Kernel 1: fused QKV projection.  A[4096,1024] @ W[1024,512] -> g_P[z]
// BM=64 BN=64 BK=16, 256 threads, 4x4 per-thread tile
// ---------------------------------------------------------------------------
__global__ __launch_bounds__(256) void qkv_gemm(
    const float* __restrict__ A,
    const float* __restrict__ Wq,
    const float* __restrict__ Wk,
    const float* __restrict__ Wv)
{
    const int which = blockIdx.z;
    const float* W = (which == 0) ? Wq : (which == 1) ? Wk : Wv;
    float* P = g_P + (size_t)which * PSZ;

    __shared__ float As[16][64 + 4];   // transposed: As[k][m]
    __shared__ float Bs[16][64];       // Bs[k][n]

    const int m0 = blockIdx.y * 64;
    const int n0 = blockIdx.x * 64;
    const int tid = threadIdx.x;

    const int arow  = tid >> 2;          // 0..63
    const int acol4 = (tid & 3) * 4;     // 0,4,8,12
    const int brow  = tid >> 4;          // 0..15
    const int bcol4 = (tid & 15) * 4;    // 0..60

    const int ty = tid >> 4;   // 0..15 (row group)
    const int tx = tid & 15;   // 0..15 (col group)

    float acc[4][4];
#pragma unroll
    for (int i = 0; i < 4; i++)
#pragma unroll
        for (int j = 0; j < 4; j++) acc[i][j] = 0.0f;

    for (int k0 = 0; k0 < INF; k0 += 16) {
        float4 a4 = *(const float4*)&A[(size_t)(m0 + arow) * INF + k0 + acol4];
        As[acol4 + 0][arow] = a4.x;
        As[acol4 + 1][arow] = a4.y;
        As[acol4 + 2][arow] = a4.z;
        As[acol4 + 3][arow] = a4.w;
        *(float4*)&Bs[brow][bcol4] =
            *(const float4*)&W[(size_t)(k0 + brow) * NP + n0 + bcol4];
        __syncthreads();

#pragma unroll
        for (int k = 0; k < 16; k++) {
            float4 a = *(const float4*)&As[k][ty * 4];
            float4 b = *(const float4*)&Bs[k][tx * 4];
            float av[4] = {a.x, a.y, a.z, a.w};
            float bv[4] = {b.x, b.y, b.z, b.w};
#pragma unroll
            for (int i = 0; i < 4; i++)
#pragma unroll
                for (int j = 0; j < 4; j++)
                    acc[i][j] = fmaf(av[i], bv[j], acc[i][j]);
        }
        __syncthreads();
    }

#pragma unroll
    for (int i = 0; i < 4; i++) {
        float4 o = make_float4(acc[i][0], acc[i][1], acc[i][2], acc[i][3]);
        *(float4*)&P[(size_t)(m0 + ty * 4 + i) * NP + n0 + tx * 4] = o;
    }
}

// ---------------------------------------------------------------------------
// Kernel 2: flash attention per (b,h).  Q,K,V are contiguous [2048,64] views:
//   head h of batch b = rows [h*256, h*256+256) of P[b] viewed as [2048,64].
// 64 threads/block, one q-row per thread. KV tiles of 64 in smem.
// Online softmax; reference quirk: attn = softmax(scores)/8 -> acc/(l*8).
// ---------------------------------------------------------------------------
__global__ __launch_bounds__(64) void attn_kernel()
{
    const int bh = blockIdx.y;          // 0..15
    const int b  = bh >> 3;
    const int h  = bh & 7;

    const size_t head_off = (size_t)b * SEQ * NP + (size_t)h * 256 * NP; // [2048,64] view
    const float* Qh = g_P + 0 * (size_t)PSZ + head_off;
    const float* Kh = g_P + 1 * (size_t)PSZ + head_off;
    const float* Vh = g_P + 2 * (size_t)PSZ + head_off;

    const int q0 = blockIdx.x * 64;
    const int t  = threadIdx.x;         // 0..63, owns q-row q0+t

    __shared__ float Ks[64][64];
    __shared__ float Vs[64][64];

    // q row in registers (64 floats)
    float4 q[16];
    {
        const float4* qg = (const float4*)&Qh[(size_t)(q0 + t) * DPH];
#pragma unroll
        for (int i = 0; i < 16; i++) q[i] = qg[i];
    }

    float4 acc[16];
#pragma unroll
    for (int i = 0; i < 16; i++) acc[i] = make_float4(0.f, 0.f, 0.f, 0.f);
    float m_i = -1e30f;
    float l_i = 0.0f;

    for (int kt = 0; kt < SEQ; kt += 64) {
        __syncthreads();
        // cooperative tile load, coalesced (tile is contiguous [64*64] floats)
        {
            const float4* Kg = (const float4*)&Kh[(size_t)kt * DPH];
            const float4* Vg = (const float4*)&Vh[(size_t)kt * DPH];
            float4* Ksm = (float4*)&Ks[0][0];
            float4* Vsm = (float4*)&Vs[0][0];
#pragma unroll
            for (int i = 0; i < 16; i++) {
                Ksm[i * 64 + t] = Kg[i * 64 + t];
                Vsm[i * 64 + t] = Vg[i * 64 + t];
            }
        }
        __syncthreads();

#pragma unroll 1
        for (int j0 = 0; j0 < 64; j0 += 16) {
            float sc[16];
#pragma unroll
            for (int j = 0; j < 16; j++) {
                const float4* kr = (const float4*)&Ks[j0 + j][0];
                float s0 = 0.f, s1 = 0.f, s2 = 0.f, s3 = 0.f;
#pragma unroll
                for (int kk = 0; kk < 16; kk++) {
                    float4 kv = kr[kk];
                    s0 = fmaf(q[kk].x, kv.x, s0);
                    s1 = fmaf(q[kk].y, kv.y, s1);
                    s2 = fmaf(q[kk].z, kv.z, s2);
                    s3 = fmaf(q[kk].w, kv.w, s3);
                }
                sc[j] = (s0 + s1) + (s2 + s3);
            }
            // online softmax update
            float mx = m_i;
#pragma unroll
            for (int j = 0; j < 16; j++) mx = fmaxf(mx, sc[j]);
            float corr = __expf(m_i - mx);
            m_i = mx;
            l_i *= corr;
#pragma unroll
            for (int i = 0; i < 16; i++) {
                acc[i].x *= corr; acc[i].y *= corr;
                acc[i].z *= corr; acc[i].w *= corr;
            }
#pragma unroll
            for (int j = 0; j < 16; j++) {
                float p = __expf(sc[j] - m_i);
                l_i += p;
                const float4* vr = (const float4*)&Vs[j0 + j][0];
#pragma unroll
                for (int i = 0; i < 16; i++) {
                    float4 vv = vr[i];
                    acc[i].x = fmaf(p, vv.x, acc[i].x);
                    acc[i].y = fmaf(p, vv.y, acc[i].y);
                    acc[i].z = fmaf(p, vv.z, acc[i].z);
                    acc[i].w = fmaf(p, vv.w, acc[i].w);
                }
            }
        }
    }

    const float inv = 1.0f / (l_i * 8.0f);   // post-softmax /sqrt(d) quirk
    float4* out = (float4*)&g_ctx[((size_t)bh * SEQ + q0 + t) * DPH];
#pragma unroll
    for (int i = 0; i < 16; i++) {
        float4 o;
        o.x = acc[i].x * inv; o.y = acc[i].y * inv;
        o.z = acc[i].z * inv; o.w = acc[i].w * inv;
        out[i] = o;
    }
}

// ---------------------------------------------------------------------------
// Kernel 3: output projection. ctx[32768,64] @ Wo[64,1024] + bo -> out
// 64x64 tile, full K=64 resident in smem, 256 threads, 4x4 per-thread tile.
// ---------------------------------------------------------------------------
__global__ __launch_bounds__(256) void out_proj(
    const float* __restrict__ Wo,
    const float* __restrict__ bo,
    float* __restrict__ out)
{
    __shared__ float Cs[64][64 + 4];   // transposed ctx tile: Cs[k][r]
    __shared__ float Ws[64][64];       // Wo tile: Ws[k][c]

    const int r0 = blockIdx.y * 64;    // over 32768 rows
    const int c0 = blockIdx.x * 64;    // over 1024 cols
    const int tid = threadIdx.x;

    // load ctx tile (contiguous 4096 floats)
    {
        const float4* src = (const float4*)&g_ctx[(size_t)r0 * DPH];
#pragma unroll
        for (int i = 0; i < 4; i++) {
            int idx = i * 256 + tid;       // float4 index 0..1023
            float4 v = src[idx];
            int r  = idx >> 4;
            int k4 = (idx & 15) * 4;
            Cs[k4 + 0][r] = v.x;
            Cs[k4 + 1][r] = v.y;
            Cs[k4 + 2][r] = v.z;
            Cs[k4 + 3][r] = v.w;
        }
    }
    // load Wo tile
    {
#pragma unroll
        for (int i = 0; i < 4; i++) {
            int idx = i * 256 + tid;       // 0..1023 float4s of the 64x64 tile
            int k  = idx >> 4;
            int c4 = (idx & 15) * 4;
            *(float4*)&Ws[k][c4] = *(const float4*)&Wo[(size_t)k * OUTF + c0 + c4];
        }
    }
    __syncthreads();

    const int ty = tid >> 4;
    const int tx = tid & 15;

    float acc[4][4];
#pragma unroll
    for (int i = 0; i < 4; i++)
#pragma unroll
        for (int j = 0; j < 4; j++) acc[i][j] = 0.0f;

#pragma unroll
    for (int k = 0; k < 64; k++) {
        float4 a = *(const float4*)&Cs[k][ty * 4];
        float4 b = *(const float4*)&Ws[k][tx * 4];
        float av[4] = {a.x, a.y, a.z, a.w};
        float bv[4] = {b.x, b.y, b.z, b.w};
#pragma unroll
        for (int i = 0; i < 4; i++)
#pragma unroll
            for (int j = 0; j < 4; j++)
                acc[i][j] = fmaf(av[i], bv[j], acc[i][j]);
    }

    float4 bias = *(const float4*)&bo[c0 + tx * 4];
#pragma unroll
    for (int i = 0; i < 4; i++) {
        float4 o;
        o.x = acc[i][0] + bias.x;
        o.y = acc[i][1] + bias.y;
        o.z = acc[i][2] + bias.z;
        o.w = acc[i][3] + bias.w;
        *(float4*)&out[(size_t)(r0 + ty * 4 + i) * OUTF + c0 + tx * 4] = o;
    }
}

// ---------------------------------------------------------------------------
extern "C" void kernel_launch(void* const* d_in, const int* in_sizes, int n_in,
                              void* d_out, int out_size)
{
    const float* inputs = (const float*)d_in[0];
    const float* Wq     = (const float*)d_in[1];
    const float* Wk     = (const float*)d_in[2];
    const float* Wv     = (const float*)d_in[3];
    const float* Wo     = (const float*)d_in[4];
    const float* bo     = (const float*)d_in[5];
    float* out = (float*)d_out;

    // 1) QKV projections: [4096,1024] @ [1024,512] x3 (grid.z)
    {
        dim3 grid(NP / 64, MROWS / 64, 3);
        qkv_gemm<<<grid, 256>>>(inputs, Wq, Wk, Wv);
    }
    // 2) attention: grid (q-tiles, b*h)
    {
        dim3 grid(SEQ / 64, BATCH * HEADS);
        attn_kernel<<<grid, 64>>>();
    }
    // 3) output projection: [32768,64] @ [64,1024] + bias
    {
        dim3 grid(OUTF / 64, CTXROWS / 64);
        out_proj<<<grid, 256>>>(Wo, bo, out);
    }
}

// round 3
// speedup vs baseline: 2.5522x; 2.5522x over previous
#include <cuda_runtime.h>
#include <cuda_bf16.h>
#include <cstdint>

// ---------------------------------------------------------------------------
// Problem constants
// ---------------------------------------------------------------------------
#define BATCH 2
#define SEQ   2048
#define INF   1024
#define HEADS 8
#define DPH   64
#define OUTF  1024
#define NP    512                 // HEADS*DPH
#define MROWS (BATCH*SEQ)         // 4096
#define PSZ   (MROWS*NP)          // elems per projection
#define CTXROWS (BATCH*HEADS*SEQ) // 32768

// Scratch (module-static device memory; no runtime allocation)
__device__ __nv_bfloat16 g_Ahi[MROWS * INF];      // inputs split hi
__device__ __nv_bfloat16 g_Alo[MROWS * INF];      // inputs split lo
__device__ __nv_bfloat16 g_Wthi[3 * NP * INF];    // W^T split hi  [n][k]
__device__ __nv_bfloat16 g_Wtlo[3 * NP * INF];    // W^T split lo
__device__ __nv_bfloat16 g_Wothi[OUTF * DPH];     // Wo^T split hi [n][k]
__device__ __nv_bfloat16 g_Wotlo[OUTF * DPH];     // Wo^T split lo
__device__ __nv_bfloat16 g_Phi[3 * PSZ];          // Q,K,V split hi
__device__ __nv_bfloat16 g_Plo[3 * PSZ];          // Q,K,V split lo
__device__ __nv_bfloat16 g_Chi[CTXROWS * DPH];    // ctx split hi
__device__ __nv_bfloat16 g_Clo[CTXROWS * DPH];    // ctx split lo

// ---------------------------------------------------------------------------
// Helpers
// ---------------------------------------------------------------------------
__device__ __forceinline__ uint32_t smem_u32(const void* p) {
    uint32_t a;
    asm("{ .reg .u64 t; cvta.to.shared.u64 t, %1; cvt.u32.u64 %0, t; }"
        : "=r"(a) : "l"(p));
    return a;
}

__device__ __forceinline__ void mma16816(float d[4], const uint32_t a[4],
                                         const uint32_t b[2], const float c[4]) {
    asm volatile(
        "mma.sync.aligned.m16n8k16.row.col.f32.bf16.bf16.f32 "
        "{%0,%1,%2,%3}, {%4,%5,%6,%7}, {%8,%9}, {%10,%11,%12,%13};"
        : "=f"(d[0]), "=f"(d[1]), "=f"(d[2]), "=f"(d[3])
        : "r"(a[0]), "r"(a[1]), "r"(a[2]), "r"(a[3]),
          "r"(b[0]), "r"(b[1]),
          "f"(c[0]), "f"(c[1]), "f"(c[2]), "f"(c[3]));
}

__device__ __forceinline__ void ldsm4(uint32_t r[4], uint32_t addr) {
    asm volatile("ldmatrix.sync.aligned.m8n8.x4.shared.b16 {%0,%1,%2,%3}, [%4];"
                 : "=r"(r[0]), "=r"(r[1]), "=r"(r[2]), "=r"(r[3]) : "r"(addr));
}
__device__ __forceinline__ void ldsm4t(uint32_t r[4], uint32_t addr) {
    asm volatile("ldmatrix.sync.aligned.m8n8.x4.trans.shared.b16 {%0,%1,%2,%3}, [%4];"
                 : "=r"(r[0]), "=r"(r[1]), "=r"(r[2]), "=r"(r[3]) : "r"(addr));
}

__device__ __forceinline__ void split1(float v, __nv_bfloat16& h, __nv_bfloat16& l) {
    h = __float2bfloat16_rn(v);
    l = __float2bfloat16_rn(v - __bfloat162float(h));
}
__device__ __forceinline__ uint32_t pack2(__nv_bfloat16 a, __nv_bfloat16 b) {
    __nv_bfloat162 p = __halves2bfloat162(a, b);
    return *reinterpret_cast<uint32_t*>(&p);
}
__device__ __forceinline__ uint2 pack4(__nv_bfloat16 a, __nv_bfloat16 b,
                                       __nv_bfloat16 c, __nv_bfloat16 d) {
    uint2 r; r.x = pack2(a, b); r.y = pack2(c, d); return r;
}

// bf16 smem row stride (elements) for mma operand tiles
#define STR 72   // 144 B per row: 16B-aligned, conflict-free ldmatrix

// ldmatrix address patterns (base_row/base_col in elements, off = byte offset of region)
// A-style x4: regs = a0..a3 of m16n8k16
__device__ __forceinline__ uint32_t addrA(uint32_t sb, int off, int brow, int bcol, int lane) {
    int row = brow + (lane & 7) + ((lane & 8) ? 8 : 0);
    int col = bcol + ((lane & 16) ? 8 : 0);
    return sb + off + (row * STR + col) * 2;
}
// B-pair x4 (non-trans): regs {0,1} = b of even n-atom, {2,3} = odd n-atom
__device__ __forceinline__ uint32_t addrB(uint32_t sb, int off, int brow, int bcol, int lane) {
    int row = brow + (lane & 7) + ((lane & 16) ? 8 : 0);
    int col = bcol + ((lane & 8) ? 8 : 0);
    return sb + off + (row * STR + col) * 2;
}
// V-trans x4: regs {0,1} = b of even d-atom, {2,3} = odd d-atom
__device__ __forceinline__ uint32_t addrV(uint32_t sb, int off, int kvrow, int dcol, int lane) {
    int row = kvrow + (lane & 7) + ((lane & 8) ? 8 : 0);
    int col = dcol + ((lane & 16) ? 8 : 0);
    return sb + off + (row * STR + col) * 2;
}

// ---------------------------------------------------------------------------
// Prep kernels: bf16 hi/lo splits and weight transposes
// ---------------------------------------------------------------------------
__global__ __launch_bounds__(256) void prep_split_A(const float* __restrict__ X) {
    int idx = blockIdx.x * blockDim.x + threadIdx.x;   // float4 index
    float4 v = ((const float4*)X)[idx];
    __nv_bfloat16 h0, h1, h2, h3, l0, l1, l2, l3;
    split1(v.x, h0, l0); split1(v.y, h1, l1);
    split1(v.z, h2, l2); split1(v.w, h3, l3);
    ((uint2*)g_Ahi)[idx] = pack4(h0, h1, h2, h3);
    ((uint2*)g_Alo)[idx] = pack4(l0, l1, l2, l3);
}

__global__ __launch_bounds__(256) void prep_Wt(const float* __restrict__ Wq,
                                               const float* __restrict__ Wk,
                                               const float* __restrict__ Wv) {
    const int which = blockIdx.z;
    const float* W = (which == 0) ? Wq : (which == 1) ? Wk : Wv;
    __shared__ float t[32][33];
    const int k0 = blockIdx.x * 32, n0 = blockIdx.y * 32;
    const int tx = threadIdx.x, ty = threadIdx.y;       // (32, 8)
#pragma unroll
    for (int j = 0; j < 4; j++)
        t[ty + j * 8][tx] = W[(size_t)(k0 + ty + j * 8) * NP + n0 + tx];
    __syncthreads();
#pragma unroll
    for (int j = 0; j < 4; j++) {
        int n = n0 + ty + j * 8, k = k0 + tx;
        float v = t[tx][ty + j * 8];
        __nv_bfloat16 h, l; split1(v, h, l);
        size_t o = ((size_t)which * NP + n) * INF + k;
        g_Wthi[o] = h; g_Wtlo[o] = l;
    }
}

__global__ __launch_bounds__(256) void prep_Wot(const float* __restrict__ Wo) {
    __shared__ float t[32][33];
    const int k0 = blockIdx.x * 32, n0 = blockIdx.y * 32;
    const int tx = threadIdx.x, ty = threadIdx.y;
#pragma unroll
    for (int j = 0; j < 4; j++)
        t[ty + j * 8][tx] = Wo[(size_t)(k0 + ty + j * 8) * OUTF + n0 + tx];
    __syncthreads();
#pragma unroll
    for (int j = 0; j < 4; j++) {
        int n = n0 + ty + j * 8, k = k0 + tx;
        float v = t[tx][ty + j * 8];
        __nv_bfloat16 h, l; split1(v, h, l);
        size_t o = (size_t)n * DPH + k;
        g_Wothi[o] = h; g_Wotlo[o] = l;
    }
}

// ---------------------------------------------------------------------------
// Kernel 1: QKV projection via mma.sync (split-bf16, 3 MMAs/product)
// Block 128x128, 8 warps (2m x 4n), warp 64x32, K chunks of 64.
// Epilogue writes split bf16 Q/K/V directly.
// ---------------------------------------------------------------------------
#define QG_AH 0
#define QG_AL (128*STR*2)
#define QG_BH (2*128*STR*2)
#define QG_BL (3*128*STR*2)
#define QG_SMEM (4*128*STR*2)     // 73728 B

__global__ __launch_bounds__(256) void qkv_mma() {
    extern __shared__ char sm[];
    uint32_t sb = smem_u32(sm);
    const int which = blockIdx.z;
    const int m0 = blockIdx.y * 128;
    const int n0 = blockIdx.x * 128;
    const int tid = threadIdx.x, wid = tid >> 5, lane = tid & 31;
    const int wm = (wid >> 2) * 64;     // warp m offset in tile
    const int wn = (wid & 3) * 32;      // warp n offset in tile

    const __nv_bfloat16* Bh = g_Wthi + (size_t)which * NP * INF;
    const __nv_bfloat16* Bl = g_Wtlo + (size_t)which * NP * INF;

    float acc[4][4][4];
#pragma unroll
    for (int mi = 0; mi < 4; mi++)
#pragma unroll
        for (int nj = 0; nj < 4; nj++)
#pragma unroll
            for (int e = 0; e < 4; e++) acc[mi][nj][e] = 0.f;

    for (int c = 0; c < 16; ++c) {
        const int k0 = c * 64;
        // load A/B chunk (hi+lo): each matrix 128 rows x 8 uint4
#pragma unroll
        for (int i = 0; i < 4; i++) {
            int idx = i * 256 + tid;
            int row = idx >> 3, v = idx & 7;
            int so = (row * STR + v * 8) * 2;
            size_t gA = (size_t)(m0 + row) * INF + k0 + v * 8;
            size_t gB = (size_t)(n0 + row) * INF + k0 + v * 8;
            *(uint4*)(sm + QG_AH + so) = *(const uint4*)(g_Ahi + gA);
            *(uint4*)(sm + QG_AL + so) = *(const uint4*)(g_Alo + gA);
            *(uint4*)(sm + QG_BH + so) = *(const uint4*)(Bh + gB);
            *(uint4*)(sm + QG_BL + so) = *(const uint4*)(Bl + gB);
        }
        __syncthreads();

#pragma unroll
        for (int ki = 0; ki < 4; ki++) {
            uint32_t bh[2][4], bl[2][4];
#pragma unroll
            for (int p = 0; p < 2; p++) {
                ldsm4(bh[p], addrB(sb, QG_BH, wn + p * 16, ki * 16, lane));
                ldsm4(bl[p], addrB(sb, QG_BL, wn + p * 16, ki * 16, lane));
            }
#pragma unroll
            for (int mi = 0; mi < 4; mi++) {
                uint32_t ah[4], al[4];
                ldsm4(ah, addrA(sb, QG_AH, wm + mi * 16, ki * 16, lane));
                ldsm4(al, addrA(sb, QG_AL, wm + mi * 16, ki * 16, lane));
#pragma unroll
                for (int nj = 0; nj < 4; nj++) {
                    const uint32_t* bhp = &bh[nj >> 1][(nj & 1) * 2];
                    const uint32_t* blp = &bl[nj >> 1][(nj & 1) * 2];
                    mma16816(acc[mi][nj], ah, bhp, acc[mi][nj]);
                    mma16816(acc[mi][nj], al, bhp, acc[mi][nj]);
                    mma16816(acc[mi][nj], ah, blp, acc[mi][nj]);
                }
            }
        }
        __syncthreads();
    }

    // epilogue: split-store to g_Phi/g_Plo
    __nv_bfloat16* Ph = g_Phi + (size_t)which * PSZ;
    __nv_bfloat16* Pl = g_Plo + (size_t)which * PSZ;
#pragma unroll
    for (int mi = 0; mi < 4; mi++) {
#pragma unroll
        for (int nj = 0; nj < 4; nj++) {
            int row = m0 + wm + mi * 16 + (lane >> 2);
            int col = n0 + wn + nj * 8 + 2 * (lane & 3);
            __nv_bfloat16 h0, h1, l0, l1;
            split1(acc[mi][nj][0], h0, l0); split1(acc[mi][nj][1], h1, l1);
            *(uint32_t*)&Ph[(size_t)row * NP + col] = pack2(h0, h1);
            *(uint32_t*)&Pl[(size_t)row * NP + col] = pack2(l0, l1);
            split1(acc[mi][nj][2], h0, l0); split1(acc[mi][nj][3], h1, l1);
            *(uint32_t*)&Ph[(size_t)(row + 8) * NP + col] = pack2(h0, h1);
            *(uint32_t*)&Pl[(size_t)(row + 8) * NP + col] = pack2(l0, l1);
        }
    }
}

// ---------------------------------------------------------------------------
// Kernel 2: flash attention via mma.sync.
// Block: one (b,h), 64 q-rows, 128 threads (4 warps x 16 rows).
// KV chunk = 64. S staged fp32 in smem; scalar online softmax (64 row-threads);
// P split bf16 in smem; PV accumulated in fragments with corr rescale.
// ---------------------------------------------------------------------------
#define AT_QH 0
#define AT_QL (64*STR*2)                 //  9216
#define AT_KH (2*64*STR*2)               // 18432
#define AT_KL (3*64*STR*2)
#define AT_VH (4*64*STR*2)
#define AT_VL (5*64*STR*2)
#define AT_S  (6*64*STR*2)               // 55296 ; fp32 [64][66]
#define SSTR 66
#define AT_PH (AT_S + 64*SSTR*4)         // 72192
#define AT_PL (AT_PH + 64*STR*2)         // 81408
#define AT_CORR (AT_PL + 64*STR*2)       // 90624
#define AT_INVL (AT_CORR + 256)          // 90880
#define AT_SMEM (AT_INVL + 256)          // 91136

__global__ __launch_bounds__(128) void attn_mma() {
    extern __shared__ char sm[];
    uint32_t sb = smem_u32(sm);
    const int bh = blockIdx.y;
    const int b = bh >> 3, h = bh & 7;
    const size_t hoff = ((size_t)b * SEQ + (size_t)h * 256) * NP;
    const __nv_bfloat16* Qh = g_Phi + hoff;
    const __nv_bfloat16* Ql = g_Plo + hoff;
    const __nv_bfloat16* Kh = g_Phi + PSZ + hoff;
    const __nv_bfloat16* Kl = g_Plo + PSZ + hoff;
    const __nv_bfloat16* Vh = g_Phi + 2 * (size_t)PSZ + hoff;
    const __nv_bfloat16* Vl = g_Plo + 2 * (size_t)PSZ + hoff;

    const int q0 = blockIdx.x * 64;
    const int tid = threadIdx.x, wid = tid >> 5, lane = tid & 31;

    float* S    = (float*)(sm + AT_S);
    float* corr = (float*)(sm + AT_CORR);
    float* invl = (float*)(sm + AT_INVL);

    // load Q block (hi/lo): 64 rows x 8 uint4 per matrix, 128 threads -> 4 each
#pragma unroll
    for (int i = 0; i < 4; i++) {
        int idx = i * 128 + tid;
        int row = idx >> 3, v = idx & 7;
        int so = (row * STR + v * 8) * 2;
        size_t g = (size_t)(q0 + row) * DPH + v * 8;
        *(uint4*)(sm + AT_QH + so) = *(const uint4*)(Qh + g);
        *(uint4*)(sm + AT_QL + so) = *(const uint4*)(Ql + g);
    }
    __syncthreads();

    // preload Q fragments (warp stripe rows 16*wid .. +15)
    uint32_t aqh[4][4], aql[4][4];
#pragma unroll
    for (int ki = 0; ki < 4; ki++) {
        ldsm4(aqh[ki], addrA(sb, AT_QH, wid * 16, ki * 16, lane));
        ldsm4(aql[ki], addrA(sb, AT_QL, wid * 16, ki * 16, lane));
    }

    float cacc[8][4];
#pragma unroll
    for (int nj = 0; nj < 8; nj++)
#pragma unroll
        for (int e = 0; e < 4; e++) cacc[nj][e] = 0.f;
    float m_i = -1e30f, l_i = 0.0f;    // valid for tid < 64 (row = tid)

    for (int kt = 0; kt < 32; kt++) {
        __syncthreads();   // prev PV done; K/V free
        // load K/V chunk (hi/lo)
#pragma unroll
        for (int i = 0; i < 4; i++) {
            int idx = i * 128 + tid;
            int row = idx >> 3, v = idx & 7;
            int so = (row * STR + v * 8) * 2;
            size_t g = (size_t)(kt * 64 + row) * DPH + v * 8;
            *(uint4*)(sm + AT_KH + so) = *(const uint4*)(Kh + g);
            *(uint4*)(sm + AT_KL + so) = *(const uint4*)(Kl + g);
            *(uint4*)(sm + AT_VH + so) = *(const uint4*)(Vh + g);
            *(uint4*)(sm + AT_VL + so) = *(const uint4*)(Vl + g);
        }
        __syncthreads();

        // S = Q @ K^T  (16 x 64 per warp)
        float sacc[8][4];
#pragma unroll
        for (int nj = 0; nj < 8; nj++)
#pragma unroll
            for (int e = 0; e < 4; e++) sacc[nj][e] = 0.f;
#pragma unroll
        for (int ki = 0; ki < 4; ki++) {
#pragma unroll
            for (int p = 0; p < 4; p++) {
                uint32_t bh2[4], bl2[4];
                ldsm4(bh2, addrB(sb, AT_KH, p * 16, ki * 16, lane));
                ldsm4(bl2, addrB(sb, AT_KL, p * 16, ki * 16, lane));
#pragma unroll
                for (int q = 0; q < 2; q++) {
                    int nj = 2 * p + q;
                    const uint32_t* bhp = &bh2[q * 2];
                    const uint32_t* blp = &bl2[q * 2];
                    mma16816(sacc[nj], aqh[ki], bhp, sacc[nj]);
                    mma16816(sacc[nj], aql[ki], bhp, sacc[nj]);
                    mma16816(sacc[nj], aqh[ki], blp, sacc[nj]);
                }
            }
        }
        // write S to smem
        {
            int r = wid * 16 + (lane >> 2);
#pragma unroll
            for (int nj = 0; nj < 8; nj++) {
                int colw = nj * 8 + 2 * (lane & 3);
                *(float2*)&S[r * SSTR + colw] = make_float2(sacc[nj][0], sacc[nj][1]);
                *(float2*)&S[(r + 8) * SSTR + colw] = make_float2(sacc[nj][2], sacc[nj][3]);
            }
        }
        __syncthreads();

        // scalar online softmax, one thread per row (tid < 64)
        if (tid < 64) {
            const float* Srow = &S[tid * SSTR];
            float mx = -1e30f;
#pragma unroll
            for (int j = 0; j < 32; j++) {
                float2 s2 = *(const float2*)&Srow[2 * j];
                mx = fmaxf(mx, fmaxf(s2.x, s2.y));
            }
            float m_new = fmaxf(m_i, mx);
            float cr = __expf(m_i - m_new);
            float lsum = 0.f;
            uint32_t* PHrow = (uint32_t*)(sm + AT_PH + tid * STR * 2);
            uint32_t* PLrow = (uint32_t*)(sm + AT_PL + tid * STR * 2);
#pragma unroll
            for (int j = 0; j < 32; j++) {
                float2 s2 = *(const float2*)&Srow[2 * j];
                float p0 = __expf(s2.x - m_new);
                float p1 = __expf(s2.y - m_new);
                lsum += p0 + p1;
                __nv_bfloat16 h0, h1, l0, l1;
                split1(p0, h0, l0); split1(p1, h1, l1);
                PHrow[j] = pack2(h0, h1);
                PLrow[j] = pack2(l0, l1);
            }
            l_i = l_i * cr + lsum;
            m_i = m_new;
            corr[tid] = cr;
        }
        __syncthreads();

        // rescale ctx acc, then PV
        {
            float cg  = corr[wid * 16 + (lane >> 2)];
            float cg8 = corr[wid * 16 + (lane >> 2) + 8];
#pragma unroll
            for (int nj = 0; nj < 8; nj++) {
                cacc[nj][0] *= cg;  cacc[nj][1] *= cg;
                cacc[nj][2] *= cg8; cacc[nj][3] *= cg8;
            }
        }
#pragma unroll
        for (int ki = 0; ki < 4; ki++) {     // kv k-atoms
            uint32_t ph[4], pl[4];
            ldsm4(ph, addrA(sb, AT_PH, wid * 16, ki * 16, lane));
            ldsm4(pl, addrA(sb, AT_PL, wid * 16, ki * 16, lane));
#pragma unroll
            for (int p = 0; p < 4; p++) {    // d pairs
                uint32_t vh2[4], vl2[4];
                ldsm4t(vh2, addrV(sb, AT_VH, ki * 16, p * 16, lane));
                ldsm4t(vl2, addrV(sb, AT_VL, ki * 16, p * 16, lane));
#pragma unroll
                for (int q = 0; q < 2; q++) {
                    int nj = 2 * p + q;
                    const uint32_t* bhp = &vh2[q * 2];
                    const uint32_t* blp = &vl2[q * 2];
                    mma16816(cacc[nj], ph, bhp, cacc[nj]);
                    mma16816(cacc[nj], pl, bhp, cacc[nj]);
                    mma16816(cacc[nj], ph, blp, cacc[nj]);
                }
            }
        }
    }

    if (tid < 64) invl[tid] = 1.0f / (8.0f * l_i);   // post-softmax /sqrt(d) quirk
    __syncthreads();

    // epilogue: ctx * invl -> split bf16 -> g_Chi/g_Clo
    {
        int r  = wid * 16 + (lane >> 2);
        float ig  = invl[r];
        float ig8 = invl[r + 8];
        size_t grow  = (size_t)bh * SEQ + q0 + r;
#pragma unroll
        for (int nj = 0; nj < 8; nj++) {
            int col = nj * 8 + 2 * (lane & 3);
            __nv_bfloat16 h0, h1, l0, l1;
            split1(cacc[nj][0] * ig, h0, l0); split1(cacc[nj][1] * ig, h1, l1);
            *(uint32_t*)&g_Chi[grow * DPH + col] = pack2(h0, h1);
            *(uint32_t*)&g_Clo[grow * DPH + col] = pack2(l0, l1);
            split1(cacc[nj][2] * ig8, h0, l0); split1(cacc[nj][3] * ig8, h1, l1);
            *(uint32_t*)&g_Chi[(grow + 8) * DPH + col] = pack2(h0, h1);
            *(uint32_t*)&g_Clo[(grow + 8) * DPH + col] = pack2(l0, l1);
        }
    }
}

// ---------------------------------------------------------------------------
// Kernel 3: output projection via mma.sync: ctx[32768,64] @ Wo[64,1024] + bo
// Block 128x128, 8 warps, single K chunk of 64.
// ---------------------------------------------------------------------------
__global__ __launch_bounds__(256) void outproj_mma(const float* __restrict__ bo,
                                                   float* __restrict__ out) {
    extern __shared__ char sm[];
    uint32_t sb = smem_u32(sm);
    const int m0 = blockIdx.y * 128;
    const int n0 = blockIdx.x * 128;
    const int tid = threadIdx.x, wid = tid >> 5, lane = tid & 31;
    const int wm = (wid >> 2) * 64;
    const int wn = (wid & 3) * 32;

    // load A (ctx) and B (Wo^T) tiles, K=64 full
#pragma unroll
    for (int i = 0; i < 4; i++) {
        int idx = i * 256 + tid;
        int row = idx >> 3, v = idx & 7;
        int so = (row * STR + v * 8) * 2;
        size_t gA = (size_t)(m0 + row) * DPH + v * 8;
        size_t gB = (size_t)(n0 + row) * DPH + v * 8;
        *(uint4*)(sm + QG_AH + so) = *(const uint4*)(g_Chi + gA);
        *(uint4*)(sm + QG_AL + so) = *(const uint4*)(g_Clo + gA);
        *(uint4*)(sm + QG_BH + so) = *(const uint4*)(g_Wothi + gB);
        *(uint4*)(sm + QG_BL + so) = *(const uint4*)(g_Wotlo + gB);
    }
    __syncthreads();

    float acc[4][4][4];
#pragma unroll
    for (int mi = 0; mi < 4; mi++)
#pragma unroll
        for (int nj = 0; nj < 4; nj++)
#pragma unroll
            for (int e = 0; e < 4; e++) acc[mi][nj][e] = 0.f;

#pragma unroll
    for (int ki = 0; ki < 4; ki++) {
        uint32_t bh[2][4], bl[2][4];
#pragma unroll
        for (int p = 0; p < 2; p++) {
            ldsm4(bh[p], addrB(sb, QG_BH, wn + p * 16, ki * 16, lane));
            ldsm4(bl[p], addrB(sb, QG_BL, wn + p * 16, ki * 16, lane));
        }
#pragma unroll
        for (int mi = 0; mi < 4; mi++) {
            uint32_t ah[4], al[4];
            ldsm4(ah, addrA(sb, QG_AH, wm + mi * 16, ki * 16, lane));
            ldsm4(al, addrA(sb, QG_AL, wm + mi * 16, ki * 16, lane));
#pragma unroll
            for (int nj = 0; nj < 4; nj++) {
                const uint32_t* bhp = &bh[nj >> 1][(nj & 1) * 2];
                const uint32_t* blp = &bl[nj >> 1][(nj & 1) * 2];
                mma16816(acc[mi][nj], ah, bhp, acc[mi][nj]);
                mma16816(acc[mi][nj], al, bhp, acc[mi][nj]);
                mma16816(acc[mi][nj], ah, blp, acc[mi][nj]);
            }
        }
    }

#pragma unroll
    for (int mi = 0; mi < 4; mi++) {
#pragma unroll
        for (int nj = 0; nj < 4; nj++) {
            int row = m0 + wm + mi * 16 + (lane >> 2);
            int col = n0 + wn + nj * 8 + 2 * (lane & 3);
            float2 bv = *(const float2*)&bo[col];
            *(float2*)&out[(size_t)row * OUTF + col] =
                make_float2(acc[mi][nj][0] + bv.x, acc[mi][nj][1] + bv.y);
            *(float2*)&out[(size_t)(row + 8) * OUTF + col] =
                make_float2(acc[mi][nj][2] + bv.x, acc[mi][nj][3] + bv.y);
        }
    }
}

// ---------------------------------------------------------------------------
extern "C" void kernel_launch(void* const* d_in, const int* in_sizes, int n_in,
                              void* d_out, int out_size)
{
    const float* inputs = (const float*)d_in[0];
    const float* Wq     = (const float*)d_in[1];
    const float* Wk     = (const float*)d_in[2];
    const float* Wv     = (const float*)d_in[3];
    const float* Wo     = (const float*)d_in[4];
    const float* bo     = (const float*)d_in[5];
    float* out = (float*)d_out;

    cudaFuncSetAttribute(qkv_mma, cudaFuncAttributeMaxDynamicSharedMemorySize, QG_SMEM);
    cudaFuncSetAttribute(attn_mma, cudaFuncAttributeMaxDynamicSharedMemorySize, AT_SMEM);
    cudaFuncSetAttribute(outproj_mma, cudaFuncAttributeMaxDynamicSharedMemorySize, QG_SMEM);

    // prep
    prep_split_A<<<(MROWS * INF / 4) / 256, 256>>>(inputs);
    {
        dim3 grid(INF / 32, NP / 32, 3);
        prep_Wt<<<grid, dim3(32, 8)>>>(Wq, Wk, Wv);
    }
    {
        dim3 grid(DPH / 32, OUTF / 32);
        prep_Wot<<<grid, dim3(32, 8)>>>(Wo);
    }
    // QKV projections
    {
        dim3 grid(NP / 128, MROWS / 128, 3);
        qkv_mma<<<grid, 256, QG_SMEM>>>();
    }
    // attention
    {
        dim3 grid(SEQ / 64, BATCH * HEADS);
        attn_mma<<<grid, 128, AT_SMEM>>>();
    }
    // output projection
    {
        dim3 grid(OUTF / 128, CTXROWS / 128);
        outproj_mma<<<grid, 256, QG_SMEM>>>(bo, out);
    }
}

// round 4
// speedup vs baseline: 3.1784x; 1.2454x over previous
#include <cuda_runtime.h>
#include <cuda_bf16.h>
#include <cstdint>

// ---------------------------------------------------------------------------
// Problem constants
// ---------------------------------------------------------------------------
#define BATCH 2
#define SEQ   2048
#define INF   1024
#define HEADS 8
#define DPH   64
#define OUTF  1024
#define NP    512                 // HEADS*DPH
#define MROWS (BATCH*SEQ)         // 4096
#define PSZ   (MROWS*NP)          // elems per projection
#define CTXROWS (BATCH*HEADS*SEQ) // 32768

// Scratch (module-static device memory; no runtime allocation)
__device__ __nv_bfloat16 g_Ahi[MROWS * INF];
__device__ __nv_bfloat16 g_Alo[MROWS * INF];
__device__ __nv_bfloat16 g_Wthi[3 * NP * INF];    // W^T split hi [n][k]
__device__ __nv_bfloat16 g_Wtlo[3 * NP * INF];
__device__ __nv_bfloat16 g_Wothi[OUTF * DPH];     // Wo^T split hi [n][k]
__device__ __nv_bfloat16 g_Wotlo[OUTF * DPH];
__device__ __nv_bfloat16 g_Phi[3 * PSZ];          // Q,K,V split hi
__device__ __nv_bfloat16 g_Plo[3 * PSZ];
__device__ __nv_bfloat16 g_Chi[CTXROWS * DPH];    // ctx split hi
__device__ __nv_bfloat16 g_Clo[CTXROWS * DPH];

// ---------------------------------------------------------------------------
// Helpers
// ---------------------------------------------------------------------------
__device__ __forceinline__ uint32_t smem_u32(const void* p) {
    uint32_t a;
    asm("{ .reg .u64 t; cvta.to.shared.u64 t, %1; cvt.u32.u64 %0, t; }"
        : "=r"(a) : "l"(p));
    return a;
}

__device__ __forceinline__ void mma16816(float d[4], const uint32_t a[4],
                                         const uint32_t b[2], const float c[4]) {
    asm volatile(
        "mma.sync.aligned.m16n8k16.row.col.f32.bf16.bf16.f32 "
        "{%0,%1,%2,%3}, {%4,%5,%6,%7}, {%8,%9}, {%10,%11,%12,%13};"
        : "=f"(d[0]), "=f"(d[1]), "=f"(d[2]), "=f"(d[3])
        : "r"(a[0]), "r"(a[1]), "r"(a[2]), "r"(a[3]),
          "r"(b[0]), "r"(b[1]),
          "f"(c[0]), "f"(c[1]), "f"(c[2]), "f"(c[3]));
}

__device__ __forceinline__ void ldsm4(uint32_t r[4], uint32_t addr) {
    asm volatile("ldmatrix.sync.aligned.m8n8.x4.shared.b16 {%0,%1,%2,%3}, [%4];"
                 : "=r"(r[0]), "=r"(r[1]), "=r"(r[2]), "=r"(r[3]) : "r"(addr));
}
__device__ __forceinline__ void ldsm4t(uint32_t r[4], uint32_t addr) {
    asm volatile("ldmatrix.sync.aligned.m8n8.x4.trans.shared.b16 {%0,%1,%2,%3}, [%4];"
                 : "=r"(r[0]), "=r"(r[1]), "=r"(r[2]), "=r"(r[3]) : "r"(addr));
}

#define CP_A16(dst, src) \
    asm volatile("cp.async.cg.shared.global [%0], [%1], 16;" :: "r"(dst), "l"(src) : "memory")
#define CP_COMMIT() asm volatile("cp.async.commit_group;" ::: "memory")
#define CP_WAIT0()  asm volatile("cp.async.wait_group 0;" ::: "memory")

__device__ __forceinline__ void split1(float v, __nv_bfloat16& h, __nv_bfloat16& l) {
    h = __float2bfloat16_rn(v);
    l = __float2bfloat16_rn(v - __bfloat162float(h));
}
__device__ __forceinline__ uint32_t pack2(__nv_bfloat16 a, __nv_bfloat16 b) {
    __nv_bfloat162 p = __halves2bfloat162(a, b);
    return *reinterpret_cast<uint32_t*>(&p);
}
__device__ __forceinline__ uint2 pack4(__nv_bfloat16 a, __nv_bfloat16 b,
                                       __nv_bfloat16 c, __nv_bfloat16 d) {
    uint2 r; r.x = pack2(a, b); r.y = pack2(c, d); return r;
}
__device__ __forceinline__ uint32_t splitpack(float a, float b) {
    __nv_bfloat16 h0, l0, h1, l1;
    split1(a, h0, l0); split1(b, h1, l1);
    return pack2(h0, h1);
}
__device__ __forceinline__ uint32_t splitpack_lo(float a, float b) {
    __nv_bfloat16 h0, l0, h1, l1;
    split1(a, h0, l0); split1(b, h1, l1);
    return pack2(l0, l1);
}

// bf16 smem row stride (elements): 144 B rows, conflict-free ldmatrix
#define STR 72

// ldmatrix address patterns. base = absolute smem addr of region.
__device__ __forceinline__ uint32_t addrA(uint32_t base, int brow, int bcol, int lane) {
    int row = brow + (lane & 7) + ((lane & 8) ? 8 : 0);
    int col = bcol + ((lane & 16) ? 8 : 0);
    return base + (row * STR + col) * 2;
}
__device__ __forceinline__ uint32_t addrB(uint32_t base, int brow, int bcol, int lane) {
    int row = brow + (lane & 7) + ((lane & 16) ? 8 : 0);
    int col = bcol + ((lane & 8) ? 8 : 0);
    return base + (row * STR + col) * 2;
}
__device__ __forceinline__ uint32_t addrV(uint32_t base, int kvrow, int dcol, int lane) {
    int row = kvrow + (lane & 7) + ((lane & 8) ? 8 : 0);
    int col = dcol + ((lane & 16) ? 8 : 0);
    return base + (row * STR + col) * 2;
}

// ---------------------------------------------------------------------------
// Prep kernels
// ---------------------------------------------------------------------------
__global__ __launch_bounds__(256) void prep_split_A(const float* __restrict__ X) {
    int idx = blockIdx.x * blockDim.x + threadIdx.x;
    float4 v = ((const float4*)X)[idx];
    __nv_bfloat16 h0, h1, h2, h3, l0, l1, l2, l3;
    split1(v.x, h0, l0); split1(v.y, h1, l1);
    split1(v.z, h2, l2); split1(v.w, h3, l3);
    ((uint2*)g_Ahi)[idx] = pack4(h0, h1, h2, h3);
    ((uint2*)g_Alo)[idx] = pack4(l0, l1, l2, l3);
}

__global__ __launch_bounds__(256) void prep_Wt(const float* __restrict__ Wq,
                                               const float* __restrict__ Wk,
                                               const float* __restrict__ Wv) {
    const int which = blockIdx.z;
    const float* W = (which == 0) ? Wq : (which == 1) ? Wk : Wv;
    __shared__ float t[32][33];
    const int k0 = blockIdx.x * 32, n0 = blockIdx.y * 32;
    const int tx = threadIdx.x, ty = threadIdx.y;
#pragma unroll
    for (int j = 0; j < 4; j++)
        t[ty + j * 8][tx] = W[(size_t)(k0 + ty + j * 8) * NP + n0 + tx];
    __syncthreads();
#pragma unroll
    for (int j = 0; j < 4; j++) {
        int n = n0 + ty + j * 8, k = k0 + tx;
        float v = t[tx][ty + j * 8];
        __nv_bfloat16 h, l; split1(v, h, l);
        size_t o = ((size_t)which * NP + n) * INF + k;
        g_Wthi[o] = h; g_Wtlo[o] = l;
    }
}

__global__ __launch_bounds__(256) void prep_Wot(const float* __restrict__ Wo) {
    __shared__ float t[32][33];
    const int k0 = blockIdx.x * 32, n0 = blockIdx.y * 32;
    const int tx = threadIdx.x, ty = threadIdx.y;
#pragma unroll
    for (int j = 0; j < 4; j++)
        t[ty + j * 8][tx] = Wo[(size_t)(k0 + ty + j * 8) * OUTF + n0 + tx];
    __syncthreads();
#pragma unroll
    for (int j = 0; j < 4; j++) {
        int n = n0 + ty + j * 8, k = k0 + tx;
        float v = t[tx][ty + j * 8];
        __nv_bfloat16 h, l; split1(v, h, l);
        size_t o = (size_t)n * DPH + k;
        g_Wothi[o] = h; g_Wotlo[o] = l;
    }
}

// ---------------------------------------------------------------------------
// Kernel 1: QKV projection, mma.sync + cp.async double-buffered K chunks.
// Block 128x128, 8 warps (2m x 4n), K chunks of 64, 2 stages.
// ---------------------------------------------------------------------------
#define Q_AH 0
#define Q_AL 18432
#define Q_BH 36864
#define Q_BL 55296
#define QST  73728                 // stage stride
#define QG_SMEM (2*QST)            // 147456

__global__ __launch_bounds__(256) void qkv_mma() {
    extern __shared__ char sm[];
    uint32_t sb = smem_u32(sm);
    const int which = blockIdx.z;
    const int m0 = blockIdx.y * 128;
    const int n0 = blockIdx.x * 128;
    const int tid = threadIdx.x, wid = tid >> 5, lane = tid & 31;
    const int wm = (wid >> 2) * 64;
    const int wn = (wid & 3) * 32;

    const __nv_bfloat16* Bh = g_Wthi + (size_t)which * NP * INF;
    const __nv_bfloat16* Bl = g_Wtlo + (size_t)which * NP * INF;

    float acc[4][4][4];
#pragma unroll
    for (int mi = 0; mi < 4; mi++)
#pragma unroll
        for (int nj = 0; nj < 4; nj++)
#pragma unroll
            for (int e = 0; e < 4; e++) acc[mi][nj][e] = 0.f;

    // chunk loader: 4 matrices x 128 rows x 8 uint4 = 4096 / 256 thr = 16 each
    auto load_chunk = [&](int c, int stage) {
        uint32_t base = sb + stage * QST;
        const int k0 = c * 64;
#pragma unroll
        for (int i = 0; i < 4; i++) {
            int idx = i * 256 + tid;
            int row = idx >> 3, v = idx & 7;
            uint32_t so = (uint32_t)(row * STR + v * 8) * 2;
            size_t gA = (size_t)(m0 + row) * INF + k0 + v * 8;
            size_t gB = (size_t)(n0 + row) * INF + k0 + v * 8;
            CP_A16(base + Q_AH + so, g_Ahi + gA);
            CP_A16(base + Q_AL + so, g_Alo + gA);
            CP_A16(base + Q_BH + so, Bh + gB);
            CP_A16(base + Q_BL + so, Bl + gB);
        }
        CP_COMMIT();
    };

    load_chunk(0, 0);

    for (int c = 0; c < 16; ++c) {
        const int s = c & 1;
        CP_WAIT0();
        __syncthreads();
        if (c < 15) load_chunk(c + 1, s ^ 1);

        uint32_t base = sb + s * QST;
#pragma unroll
        for (int ki = 0; ki < 4; ki++) {
            uint32_t bh[2][4], bl[2][4];
#pragma unroll
            for (int p = 0; p < 2; p++) {
                ldsm4(bh[p], addrB(base + Q_BH, wn + p * 16, ki * 16, lane));
                ldsm4(bl[p], addrB(base + Q_BL, wn + p * 16, ki * 16, lane));
            }
#pragma unroll
            for (int mi = 0; mi < 4; mi++) {
                uint32_t ah[4], al[4];
                ldsm4(ah, addrA(base + Q_AH, wm + mi * 16, ki * 16, lane));
                ldsm4(al, addrA(base + Q_AL, wm + mi * 16, ki * 16, lane));
#pragma unroll
                for (int nj = 0; nj < 4; nj++) {
                    const uint32_t* bhp = &bh[nj >> 1][(nj & 1) * 2];
                    const uint32_t* blp = &bl[nj >> 1][(nj & 1) * 2];
                    mma16816(acc[mi][nj], ah, bhp, acc[mi][nj]);
                    mma16816(acc[mi][nj], al, bhp, acc[mi][nj]);
                    mma16816(acc[mi][nj], ah, blp, acc[mi][nj]);
                }
            }
        }
    }

    // epilogue: split-store Q/K/V
    __nv_bfloat16* Ph = g_Phi + (size_t)which * PSZ;
    __nv_bfloat16* Pl = g_Plo + (size_t)which * PSZ;
#pragma unroll
    for (int mi = 0; mi < 4; mi++) {
#pragma unroll
        for (int nj = 0; nj < 4; nj++) {
            int row = m0 + wm + mi * 16 + (lane >> 2);
            int col = n0 + wn + nj * 8 + 2 * (lane & 3);
            *(uint32_t*)&Ph[(size_t)row * NP + col] = splitpack(acc[mi][nj][0], acc[mi][nj][1]);
            *(uint32_t*)&Pl[(size_t)row * NP + col] = splitpack_lo(acc[mi][nj][0], acc[mi][nj][1]);
            *(uint32_t*)&Ph[(size_t)(row + 8) * NP + col] = splitpack(acc[mi][nj][2], acc[mi][nj][3]);
            *(uint32_t*)&Pl[(size_t)(row + 8) * NP + col] = splitpack_lo(acc[mi][nj][2], acc[mi][nj][3]);
        }
    }
}

// ---------------------------------------------------------------------------
// Kernel 2: FA2-style flash attention.
// Block: one (b,h), 128 q-rows, 256 threads (8 warps x 16 rows each).
// KV chunks of 64, cp.async double-buffered. Softmax fully in registers
// (C-fragment == A-fragment layout); P packed straight into A-fragments.
// ---------------------------------------------------------------------------
#define A_KH 0
#define A_KL 9216
#define A_VH 18432
#define A_VL 27648
#define AST  36864                 // stage stride
#define AT_SMEM (2*AST)            // 73728

__global__ __launch_bounds__(256) void attn_fa2() {
    extern __shared__ char sm[];
    uint32_t sb = smem_u32(sm);
    const int bh = blockIdx.y;
    const int b = bh >> 3, h = bh & 7;
    const size_t hoff = ((size_t)b * SEQ + (size_t)h * 256) * NP;
    const __nv_bfloat16* Qh = g_Phi + hoff;
    const __nv_bfloat16* Ql = g_Plo + hoff;
    const __nv_bfloat16* Kh = g_Phi + PSZ + hoff;
    const __nv_bfloat16* Kl = g_Plo + PSZ + hoff;
    const __nv_bfloat16* Vh = g_Phi + 2 * (size_t)PSZ + hoff;
    const __nv_bfloat16* Vl = g_Plo + 2 * (size_t)PSZ + hoff;

    const int q0 = blockIdx.x * 128;
    const int tid = threadIdx.x, wid = tid >> 5, lane = tid & 31;

    // KV chunk loader (cp.async): 4 matrices x 64 rows x 8 uint4 = 2048/256 = 8 each
    auto load_kv = [&](int kt, int stage) {
        uint32_t base = sb + stage * AST;
#pragma unroll
        for (int i = 0; i < 2; i++) {
            int idx = i * 256 + tid;
            int row = idx >> 3, v = idx & 7;
            uint32_t so = (uint32_t)(row * STR + v * 8) * 2;
            size_t g = (size_t)(kt * 64 + row) * DPH + v * 8;
            CP_A16(base + A_KH + so, Kh + g);
            CP_A16(base + A_KL + so, Kl + g);
            CP_A16(base + A_VH + so, Vh + g);
            CP_A16(base + A_VL + so, Vl + g);
        }
        CP_COMMIT();
    };

    // Stage Q (128 rows x 64) into stage-1 area, then keep fragments in regs.
    {
#pragma unroll
        for (int i = 0; i < 4; i++) {
            int idx = i * 256 + tid;
            int row = idx >> 3, v = idx & 7;
            uint32_t so = (uint32_t)(row * STR + v * 8) * 2;
            size_t g = (size_t)(q0 + row) * DPH + v * 8;
            *(uint4*)(sm + AST + 0     + so) = *(const uint4*)(Qh + g);
            *(uint4*)(sm + AST + 18432 + so) = *(const uint4*)(Ql + g);
        }
    }
    load_kv(0, 0);
    __syncthreads();

    uint32_t aqh[4][4], aql[4][4];
#pragma unroll
    for (int ki = 0; ki < 4; ki++) {
        ldsm4(aqh[ki], addrA(sb + AST + 0,     wid * 16, ki * 16, lane));
        ldsm4(aql[ki], addrA(sb + AST + 18432, wid * 16, ki * 16, lane));
    }
    __syncthreads();   // Q staging consumed before iter0 writes stage 1

    float cacc[8][4];
#pragma unroll
    for (int nj = 0; nj < 8; nj++)
#pragma unroll
        for (int e = 0; e < 4; e++) cacc[nj][e] = 0.f;
    float m0 = -1e30f, m1 = -1e30f, l0 = 0.f, l1 = 0.f;

    for (int kt = 0; kt < 32; kt++) {
        const int s = kt & 1;
        CP_WAIT0();
        __syncthreads();
        if (kt < 31) load_kv(kt + 1, s ^ 1);

        uint32_t base = sb + s * AST;

        // S = Q @ K^T  (16 x 64 per warp)
        float sacc[8][4];
#pragma unroll
        for (int nj = 0; nj < 8; nj++)
#pragma unroll
            for (int e = 0; e < 4; e++) sacc[nj][e] = 0.f;
#pragma unroll
        for (int ki = 0; ki < 4; ki++) {
#pragma unroll
            for (int p = 0; p < 4; p++) {
                uint32_t kh2[4], kl2[4];
                ldsm4(kh2, addrB(base + A_KH, p * 16, ki * 16, lane));
                ldsm4(kl2, addrB(base + A_KL, p * 16, ki * 16, lane));
#pragma unroll
                for (int q = 0; q < 2; q++) {
                    int nj = 2 * p + q;
                    mma16816(sacc[nj], aqh[ki], &kh2[q * 2], sacc[nj]);
                    mma16816(sacc[nj], aql[ki], &kh2[q * 2], sacc[nj]);
                    mma16816(sacc[nj], aqh[ki], &kl2[q * 2], sacc[nj]);
                }
            }
        }

        // register softmax: rows r=lane>>2 (m0/l0) and r+8 (m1/l1)
        float mx0 = -1e30f, mx1 = -1e30f;
#pragma unroll
        for (int nj = 0; nj < 8; nj++) {
            mx0 = fmaxf(mx0, fmaxf(sacc[nj][0], sacc[nj][1]));
            mx1 = fmaxf(mx1, fmaxf(sacc[nj][2], sacc[nj][3]));
        }
        mx0 = fmaxf(mx0, __shfl_xor_sync(0xffffffffu, mx0, 1));
        mx0 = fmaxf(mx0, __shfl_xor_sync(0xffffffffu, mx0, 2));
        mx1 = fmaxf(mx1, __shfl_xor_sync(0xffffffffu, mx1, 1));
        mx1 = fmaxf(mx1, __shfl_xor_sync(0xffffffffu, mx1, 2));
        float mn0 = fmaxf(m0, mx0), mn1 = fmaxf(m1, mx1);
        float c0 = __expf(m0 - mn0), c1 = __expf(m1 - mn1);
        m0 = mn0; m1 = mn1;

        uint32_t aPh[4][4], aPl[4][4];
        float ls0 = 0.f, ls1 = 0.f;
#pragma unroll
        for (int ki = 0; ki < 4; ki++) {
#pragma unroll
            for (int jj = 0; jj < 2; jj++) {
                int nj = 2 * ki + jj;
                float p0 = __expf(sacc[nj][0] - mn0);
                float p1 = __expf(sacc[nj][1] - mn0);
                float p2 = __expf(sacc[nj][2] - mn1);
                float p3 = __expf(sacc[nj][3] - mn1);
                ls0 += p0 + p1; ls1 += p2 + p3;
                aPh[ki][2 * jj + 0] = splitpack(p0, p1);
                aPh[ki][2 * jj + 1] = splitpack(p2, p3);
                aPl[ki][2 * jj + 0] = splitpack_lo(p0, p1);
                aPl[ki][2 * jj + 1] = splitpack_lo(p2, p3);
            }
        }
        ls0 += __shfl_xor_sync(0xffffffffu, ls0, 1);
        ls0 += __shfl_xor_sync(0xffffffffu, ls0, 2);
        ls1 += __shfl_xor_sync(0xffffffffu, ls1, 1);
        ls1 += __shfl_xor_sync(0xffffffffu, ls1, 2);
        l0 = l0 * c0 + ls0;
        l1 = l1 * c1 + ls1;

#pragma unroll
        for (int nj = 0; nj < 8; nj++) {
            cacc[nj][0] *= c0; cacc[nj][1] *= c0;
            cacc[nj][2] *= c1; cacc[nj][3] *= c1;
        }

        // PV
#pragma unroll
        for (int ki = 0; ki < 4; ki++) {
#pragma unroll
            for (int p = 0; p < 4; p++) {
                uint32_t vh2[4], vl2[4];
                ldsm4t(vh2, addrV(base + A_VH, ki * 16, p * 16, lane));
                ldsm4t(vl2, addrV(base + A_VL, ki * 16, p * 16, lane));
#pragma unroll
                for (int q = 0; q < 2; q++) {
                    int nj = 2 * p + q;
                    mma16816(cacc[nj], aPh[ki], &vh2[q * 2], cacc[nj]);
                    mma16816(cacc[nj], aPl[ki], &vh2[q * 2], cacc[nj]);
                    mma16816(cacc[nj], aPh[ki], &vl2[q * 2], cacc[nj]);
                }
            }
        }
    }

    // epilogue: /(8*l), split-store ctx
    float inv0 = 1.0f / (8.0f * l0);
    float inv1 = 1.0f / (8.0f * l1);
    {
        int r = wid * 16 + (lane >> 2);
        size_t grow = (size_t)bh * SEQ + q0 + r;
#pragma unroll
        for (int nj = 0; nj < 8; nj++) {
            int col = nj * 8 + 2 * (lane & 3);
            float a0 = cacc[nj][0] * inv0, a1 = cacc[nj][1] * inv0;
            float a2 = cacc[nj][2] * inv1, a3 = cacc[nj][3] * inv1;
            *(uint32_t*)&g_Chi[grow * DPH + col]       = splitpack(a0, a1);
            *(uint32_t*)&g_Clo[grow * DPH + col]       = splitpack_lo(a0, a1);
            *(uint32_t*)&g_Chi[(grow + 8) * DPH + col] = splitpack(a2, a3);
            *(uint32_t*)&g_Clo[(grow + 8) * DPH + col] = splitpack_lo(a2, a3);
        }
    }
}

// ---------------------------------------------------------------------------
// Kernel 3: output projection: ctx[32768,64] @ Wo[64,1024] + bo
// Block 128x128, 8 warps, single K chunk of 64.
// ---------------------------------------------------------------------------
__global__ __launch_bounds__(256) void outproj_mma(const float* __restrict__ bo,
                                                   float* __restrict__ out) {
    extern __shared__ char sm[];
    uint32_t sb = smem_u32(sm);
    const int m0 = blockIdx.y * 128;
    const int n0 = blockIdx.x * 128;
    const int tid = threadIdx.x, wid = tid >> 5, lane = tid & 31;
    const int wm = (wid >> 2) * 64;
    const int wn = (wid & 3) * 32;

#pragma unroll
    for (int i = 0; i < 4; i++) {
        int idx = i * 256 + tid;
        int row = idx >> 3, v = idx & 7;
        uint32_t so = (uint32_t)(row * STR + v * 8) * 2;
        size_t gA = (size_t)(m0 + row) * DPH + v * 8;
        size_t gB = (size_t)(n0 + row) * DPH + v * 8;
        CP_A16(sb + Q_AH + so, g_Chi + gA);
        CP_A16(sb + Q_AL + so, g_Clo + gA);
        CP_A16(sb + Q_BH + so, g_Wothi + gB);
        CP_A16(sb + Q_BL + so, g_Wotlo + gB);
    }
    CP_COMMIT();
    CP_WAIT0();
    __syncthreads();

    float acc[4][4][4];
#pragma unroll
    for (int mi = 0; mi < 4; mi++)
#pragma unroll
        for (int nj = 0; nj < 4; nj++)
#pragma unroll
            for (int e = 0; e < 4; e++) acc[mi][nj][e] = 0.f;

#pragma unroll
    for (int ki = 0; ki < 4; ki++) {
        uint32_t bh[2][4], bl[2][4];
#pragma unroll
        for (int p = 0; p < 2; p++) {
            ldsm4(bh[p], addrB(sb + Q_BH, wn + p * 16, ki * 16, lane));
            ldsm4(bl[p], addrB(sb + Q_BL, wn + p * 16, ki * 16, lane));
        }
#pragma unroll
        for (int mi = 0; mi < 4; mi++) {
            uint32_t ah[4], al[4];
            ldsm4(ah, addrA(sb + Q_AH, wm + mi * 16, ki * 16, lane));
            ldsm4(al, addrA(sb + Q_AL, wm + mi * 16, ki * 16, lane));
#pragma unroll
            for (int nj = 0; nj < 4; nj++) {
                const uint32_t* bhp = &bh[nj >> 1][(nj & 1) * 2];
                const uint32_t* blp = &bl[nj >> 1][(nj & 1) * 2];
                mma16816(acc[mi][nj], ah, bhp, acc[mi][nj]);
                mma16816(acc[mi][nj], al, bhp, acc[mi][nj]);
                mma16816(acc[mi][nj], ah, blp, acc[mi][nj]);
            }
        }
    }

#pragma unroll
    for (int mi = 0; mi < 4; mi++) {
#pragma unroll
        for (int nj = 0; nj < 4; nj++) {
            int row = m0 + wm + mi * 16 + (lane >> 2);
            int col = n0 + wn + nj * 8 + 2 * (lane & 3);
            float2 bv = *(const float2*)&bo[col];
            *(float2*)&out[(size_t)row * OUTF + col] =
                make_float2(acc[mi][nj][0] + bv.x, acc[mi][nj][1] + bv.y);
            *(float2*)&out[(size_t)(row + 8) * OUTF + col] =
                make_float2(acc[mi][nj][2] + bv.x, acc[mi][nj][3] + bv.y);
        }
    }
}

// ---------------------------------------------------------------------------
extern "C" void kernel_launch(void* const* d_in, const int* in_sizes, int n_in,
                              void* d_out, int out_size)
{
    const float* inputs = (const float*)d_in[0];
    const float* Wq     = (const float*)d_in[1];
    const float* Wk     = (const float*)d_in[2];
    const float* Wv     = (const float*)d_in[3];
    const float* Wo     = (const float*)d_in[4];
    const float* bo     = (const float*)d_in[5];
    float* out = (float*)d_out;

    cudaFuncSetAttribute(qkv_mma, cudaFuncAttributeMaxDynamicSharedMemorySize, QG_SMEM);
    cudaFuncSetAttribute(attn_fa2, cudaFuncAttributeMaxDynamicSharedMemorySize, AT_SMEM);
    cudaFuncSetAttribute(outproj_mma, cudaFuncAttributeMaxDynamicSharedMemorySize, QST);

    prep_split_A<<<(MROWS * INF / 4) / 256, 256>>>(inputs);
    {
        dim3 grid(INF / 32, NP / 32, 3);
        prep_Wt<<<grid, dim3(32, 8)>>>(Wq, Wk, Wv);
    }
    {
        dim3 grid(DPH / 32, OUTF / 32);
        prep_Wot<<<grid, dim3(32, 8)>>>(Wo);
    }
    {
        dim3 grid(NP / 128, MROWS / 128, 3);
        qkv_mma<<<grid, 256, QG_SMEM>>>();
    }
    {
        dim3 grid(SEQ / 128, BATCH * HEADS);
        attn_fa2<<<grid, 256, AT_SMEM>>>();
    }
    {
        dim3 grid(OUTF / 128, CTXROWS / 128);
        outproj_mma<<<grid, 256, QST>>>(bo, out);
    }
}

// round 5
// speedup vs baseline: 3.3338x; 1.0489x over previous
#include <cuda_runtime.h>
#include <cuda_bf16.h>
#include <cstdint>

// ---------------------------------------------------------------------------
// Problem constants
// ---------------------------------------------------------------------------
#define BATCH 2
#define SEQ   2048
#define INF   1024
#define HEADS 8
#define DPH   64
#define OUTF  1024
#define NP    512                 // HEADS*DPH
#define MROWS (BATCH*SEQ)         // 4096
#define PSZ   (MROWS*NP)          // elems per projection
#define CTXROWS (BATCH*HEADS*SEQ) // 32768

// Scratch (module-static device memory; no runtime allocation)
__device__ __nv_bfloat16 g_Ahi[MROWS * INF];
__device__ __nv_bfloat16 g_Alo[MROWS * INF];
__device__ __nv_bfloat16 g_Wthi[3 * NP * INF];    // W^T split hi [n][k]
__device__ __nv_bfloat16 g_Wtlo[3 * NP * INF];
__device__ __nv_bfloat16 g_Wothi[OUTF * DPH];     // Wo^T split hi [n][k]
__device__ __nv_bfloat16 g_Wotlo[OUTF * DPH];
__device__ __nv_bfloat16 g_Phi[3 * PSZ];          // Q,K,V split hi
__device__ __nv_bfloat16 g_Plo[3 * PSZ];
__device__ __nv_bfloat16 g_Chi[CTXROWS * DPH];    // ctx split hi
__device__ __nv_bfloat16 g_Clo[CTXROWS * DPH];

// ---------------------------------------------------------------------------
// Helpers
// ---------------------------------------------------------------------------
__device__ __forceinline__ uint32_t smem_u32(const void* p) {
    uint32_t a;
    asm("{ .reg .u64 t; cvta.to.shared.u64 t, %1; cvt.u32.u64 %0, t; }"
        : "=r"(a) : "l"(p));
    return a;
}

__device__ __forceinline__ void mma16816(float d[4], const uint32_t a[4],
                                         const uint32_t b[2], const float c[4]) {
    asm volatile(
        "mma.sync.aligned.m16n8k16.row.col.f32.bf16.bf16.f32 "
        "{%0,%1,%2,%3}, {%4,%5,%6,%7}, {%8,%9}, {%10,%11,%12,%13};"
        : "=f"(d[0]), "=f"(d[1]), "=f"(d[2]), "=f"(d[3])
        : "r"(a[0]), "r"(a[1]), "r"(a[2]), "r"(a[3]),
          "r"(b[0]), "r"(b[1]),
          "f"(c[0]), "f"(c[1]), "f"(c[2]), "f"(c[3]));
}

__device__ __forceinline__ void ldsm4(uint32_t r[4], uint32_t addr) {
    asm volatile("ldmatrix.sync.aligned.m8n8.x4.shared.b16 {%0,%1,%2,%3}, [%4];"
                 : "=r"(r[0]), "=r"(r[1]), "=r"(r[2]), "=r"(r[3]) : "r"(addr));
}
__device__ __forceinline__ void ldsm4t(uint32_t r[4], uint32_t addr) {
    asm volatile("ldmatrix.sync.aligned.m8n8.x4.trans.shared.b16 {%0,%1,%2,%3}, [%4];"
                 : "=r"(r[0]), "=r"(r[1]), "=r"(r[2]), "=r"(r[3]) : "r"(addr));
}

#define CP_A16(dst, src) \
    asm volatile("cp.async.cg.shared.global [%0], [%1], 16;" :: "r"(dst), "l"(src) : "memory")
#define CP_COMMIT() asm volatile("cp.async.commit_group;" ::: "memory")
#define CP_WAIT0()  asm volatile("cp.async.wait_group 0;" ::: "memory")

__device__ __forceinline__ void split1(float v, __nv_bfloat16& h, __nv_bfloat16& l) {
    h = __float2bfloat16_rn(v);
    l = __float2bfloat16_rn(v - __bfloat162float(h));
}
__device__ __forceinline__ uint32_t pack2(__nv_bfloat16 a, __nv_bfloat16 b) {
    __nv_bfloat162 p = __halves2bfloat162(a, b);
    return *reinterpret_cast<uint32_t*>(&p);
}
__device__ __forceinline__ uint2 pack4(__nv_bfloat16 a, __nv_bfloat16 b,
                                       __nv_bfloat16 c, __nv_bfloat16 d) {
    uint2 r; r.x = pack2(a, b); r.y = pack2(c, d); return r;
}
__device__ __forceinline__ uint32_t splitpack(float a, float b) {
    __nv_bfloat16 h0, l0, h1, l1;
    split1(a, h0, l0); split1(b, h1, l1);
    return pack2(h0, h1);
}
__device__ __forceinline__ uint32_t splitpack_lo(float a, float b) {
    __nv_bfloat16 h0, l0, h1, l1;
    split1(a, h0, l0); split1(b, h1, l1);
    return pack2(l0, l1);
}

// strides (elements) for mma operand tiles in smem
#define STR  72   // 144 B rows (64-col tiles)
#define STR2 40   // 80 B rows (32-col tiles); 8-row ldsm stride 20 banks -> conflict-free

__device__ __forceinline__ uint32_t addrA_s(uint32_t base, int brow, int bcol, int lane, int str) {
    int row = brow + (lane & 7) + ((lane & 8) ? 8 : 0);
    int col = bcol + ((lane & 16) ? 8 : 0);
    return base + (row * str + col) * 2;
}
__device__ __forceinline__ uint32_t addrB_s(uint32_t base, int brow, int bcol, int lane, int str) {
    int row = brow + (lane & 7) + ((lane & 16) ? 8 : 0);
    int col = bcol + ((lane & 8) ? 8 : 0);
    return base + (row * str + col) * 2;
}
__device__ __forceinline__ uint32_t addrV_s(uint32_t base, int kvrow, int dcol, int lane, int str) {
    int row = kvrow + (lane & 7) + ((lane & 8) ? 8 : 0);
    int col = dcol + ((lane & 16) ? 8 : 0);
    return base + (row * str + col) * 2;
}

// ---------------------------------------------------------------------------
// Prep kernels
// ---------------------------------------------------------------------------
__global__ __launch_bounds__(256) void prep_split_A(const float* __restrict__ X) {
    int idx = blockIdx.x * blockDim.x + threadIdx.x;
    float4 v = ((const float4*)X)[idx];
    __nv_bfloat16 h0, h1, h2, h3, l0, l1, l2, l3;
    split1(v.x, h0, l0); split1(v.y, h1, l1);
    split1(v.z, h2, l2); split1(v.w, h3, l3);
    ((uint2*)g_Ahi)[idx] = pack4(h0, h1, h2, h3);
    ((uint2*)g_Alo)[idx] = pack4(l0, l1, l2, l3);
}

__global__ __launch_bounds__(256) void prep_Wt(const float* __restrict__ Wq,
                                               const float* __restrict__ Wk,
                                               const float* __restrict__ Wv) {
    const int which = blockIdx.z;
    const float* W = (which == 0) ? Wq : (which == 1) ? Wk : Wv;
    __shared__ float t[32][33];
    const int k0 = blockIdx.x * 32, n0 = blockIdx.y * 32;
    const int tx = threadIdx.x, ty = threadIdx.y;
#pragma unroll
    for (int j = 0; j < 4; j++)
        t[ty + j * 8][tx] = W[(size_t)(k0 + ty + j * 8) * NP + n0 + tx];
    __syncthreads();
#pragma unroll
    for (int j = 0; j < 4; j++) {
        int n = n0 + ty + j * 8, k = k0 + tx;
        float v = t[tx][ty + j * 8];
        __nv_bfloat16 h, l; split1(v, h, l);
        size_t o = ((size_t)which * NP + n) * INF + k;
        g_Wthi[o] = h; g_Wtlo[o] = l;
    }
}

__global__ __launch_bounds__(256) void prep_Wot(const float* __restrict__ Wo) {
    __shared__ float t[32][33];
    const int k0 = blockIdx.x * 32, n0 = blockIdx.y * 32;
    const int tx = threadIdx.x, ty = threadIdx.y;
#pragma unroll
    for (int j = 0; j < 4; j++)
        t[ty + j * 8][tx] = Wo[(size_t)(k0 + ty + j * 8) * OUTF + n0 + tx];
    __syncthreads();
#pragma unroll
    for (int j = 0; j < 4; j++) {
        int n = n0 + ty + j * 8, k = k0 + tx;
        float v = t[tx][ty + j * 8];
        __nv_bfloat16 h, l; split1(v, h, l);
        size_t o = (size_t)n * DPH + k;
        g_Wothi[o] = h; g_Wotlo[o] = l;
    }
}

// ---------------------------------------------------------------------------
// Kernel 1: QKV projection. Block 128x128, 8 warps, K chunks of 32, 2 stages,
// 2 CTAs/SM (smem 2x40960, regs capped at 128).
// ---------------------------------------------------------------------------
#define Q2_MAT (128*STR2*2)        // 10240 per matrix
#define Q2_AH 0
#define Q2_AL Q2_MAT
#define Q2_BH (2*Q2_MAT)
#define Q2_BL (3*Q2_MAT)
#define Q2ST  (4*Q2_MAT)           // 40960 stage stride
#define QG_SMEM (2*Q2ST)           // 81920

__global__ __launch_bounds__(256, 2) void qkv_mma() {
    extern __shared__ char sm[];
    uint32_t sb = smem_u32(sm);
    const int which = blockIdx.z;
    const int m0 = blockIdx.y * 128;
    const int n0 = blockIdx.x * 128;
    const int tid = threadIdx.x, wid = tid >> 5, lane = tid & 31;
    const int wm = (wid >> 2) * 64;
    const int wn = (wid & 3) * 32;

    const __nv_bfloat16* Bh = g_Wthi + (size_t)which * NP * INF;
    const __nv_bfloat16* Bl = g_Wtlo + (size_t)which * NP * INF;

    float acc[4][4][4];
#pragma unroll
    for (int mi = 0; mi < 4; mi++)
#pragma unroll
        for (int nj = 0; nj < 4; nj++)
#pragma unroll
            for (int e = 0; e < 4; e++) acc[mi][nj][e] = 0.f;

    // chunk loader: 4 matrices x 128 rows x 4 uint4 = 2048 / 256 thr = 8 each
    auto load_chunk = [&](int c, int stage) {
        uint32_t base = sb + stage * Q2ST;
        const int k0 = c * 32;
#pragma unroll
        for (int i = 0; i < 2; i++) {
            int idx = i * 256 + tid;
            int row = idx >> 2, v = idx & 3;
            uint32_t so = (uint32_t)(row * STR2 + v * 8) * 2;
            size_t gA = (size_t)(m0 + row) * INF + k0 + v * 8;
            size_t gB = (size_t)(n0 + row) * INF + k0 + v * 8;
            CP_A16(base + Q2_AH + so, g_Ahi + gA);
            CP_A16(base + Q2_AL + so, g_Alo + gA);
            CP_A16(base + Q2_BH + so, Bh + gB);
            CP_A16(base + Q2_BL + so, Bl + gB);
        }
        CP_COMMIT();
    };

    load_chunk(0, 0);

    for (int c = 0; c < 32; ++c) {
        const int s = c & 1;
        CP_WAIT0();
        __syncthreads();
        if (c < 31) load_chunk(c + 1, s ^ 1);

        uint32_t base = sb + s * Q2ST;
#pragma unroll
        for (int ki = 0; ki < 2; ki++) {
            uint32_t bh[2][4], bl[2][4];
#pragma unroll
            for (int p = 0; p < 2; p++) {
                ldsm4(bh[p], addrB_s(base + Q2_BH, wn + p * 16, ki * 16, lane, STR2));
                ldsm4(bl[p], addrB_s(base + Q2_BL, wn + p * 16, ki * 16, lane, STR2));
            }
#pragma unroll
            for (int mi = 0; mi < 4; mi++) {
                uint32_t ah[4], al[4];
                ldsm4(ah, addrA_s(base + Q2_AH, wm + mi * 16, ki * 16, lane, STR2));
                ldsm4(al, addrA_s(base + Q2_AL, wm + mi * 16, ki * 16, lane, STR2));
#pragma unroll
                for (int nj = 0; nj < 4; nj++) {
                    const uint32_t* bhp = &bh[nj >> 1][(nj & 1) * 2];
                    const uint32_t* blp = &bl[nj >> 1][(nj & 1) * 2];
                    mma16816(acc[mi][nj], ah, bhp, acc[mi][nj]);
                    mma16816(acc[mi][nj], al, bhp, acc[mi][nj]);
                    mma16816(acc[mi][nj], ah, blp, acc[mi][nj]);
                }
            }
        }
    }

    __nv_bfloat16* Ph = g_Phi + (size_t)which * PSZ;
    __nv_bfloat16* Pl = g_Plo + (size_t)which * PSZ;
#pragma unroll
    for (int mi = 0; mi < 4; mi++) {
#pragma unroll
        for (int nj = 0; nj < 4; nj++) {
            int row = m0 + wm + mi * 16 + (lane >> 2);
            int col = n0 + wn + nj * 8 + 2 * (lane & 3);
            *(uint32_t*)&Ph[(size_t)row * NP + col] = splitpack(acc[mi][nj][0], acc[mi][nj][1]);
            *(uint32_t*)&Pl[(size_t)row * NP + col] = splitpack_lo(acc[mi][nj][0], acc[mi][nj][1]);
            *(uint32_t*)&Ph[(size_t)(row + 8) * NP + col] = splitpack(acc[mi][nj][2], acc[mi][nj][3]);
            *(uint32_t*)&Pl[(size_t)(row + 8) * NP + col] = splitpack_lo(acc[mi][nj][2], acc[mi][nj][3]);
        }
    }
}

// ---------------------------------------------------------------------------
// Kernel 2: FA2 flash attention. 128 q-rows, 256 threads, KV chunks of 64
// double-buffered; persistent Q smem region; Q-lo fragment reloaded per chunk
// to cap regs at 128 -> 2 CTAs/SM.
// ---------------------------------------------------------------------------
#define AQ_H 0
#define AQ_L 18432
#define A_KV0 36864                 // KV stages base
#define A_KH 0
#define A_KL 9216
#define A_VH 18432
#define A_VL 27648
#define AST  36864                  // stage stride
#define AT_SMEM (A_KV0 + 2*AST)     // 110592

__global__ __launch_bounds__(256, 2) void attn_fa2() {
    extern __shared__ char sm[];
    uint32_t sb = smem_u32(sm);
    const int bh = blockIdx.y;
    const int b = bh >> 3, h = bh & 7;
    const size_t hoff = ((size_t)b * SEQ + (size_t)h * 256) * NP;
    const __nv_bfloat16* Qh = g_Phi + hoff;
    const __nv_bfloat16* Ql = g_Plo + hoff;
    const __nv_bfloat16* Kh = g_Phi + PSZ + hoff;
    const __nv_bfloat16* Kl = g_Plo + PSZ + hoff;
    const __nv_bfloat16* Vh = g_Phi + 2 * (size_t)PSZ + hoff;
    const __nv_bfloat16* Vl = g_Plo + 2 * (size_t)PSZ + hoff;

    const int q0 = blockIdx.x * 128;
    const int tid = threadIdx.x, wid = tid >> 5, lane = tid & 31;

    auto load_kv = [&](int kt, int stage) {
        uint32_t base = sb + A_KV0 + stage * AST;
#pragma unroll
        for (int i = 0; i < 2; i++) {
            int idx = i * 256 + tid;
            int row = idx >> 3, v = idx & 7;
            uint32_t so = (uint32_t)(row * STR + v * 8) * 2;
            size_t g = (size_t)(kt * 64 + row) * DPH + v * 8;
            CP_A16(base + A_KH + so, Kh + g);
            CP_A16(base + A_KL + so, Kl + g);
            CP_A16(base + A_VH + so, Vh + g);
            CP_A16(base + A_VL + so, Vl + g);
        }
        CP_COMMIT();
    };

    // Persistent Q region (hi + lo)
#pragma unroll
    for (int i = 0; i < 4; i++) {
        int idx = i * 256 + tid;
        int row = idx >> 3, v = idx & 7;
        uint32_t so = (uint32_t)(row * STR + v * 8) * 2;
        size_t g = (size_t)(q0 + row) * DPH + v * 8;
        *(uint4*)(sm + AQ_H + so) = *(const uint4*)(Qh + g);
        *(uint4*)(sm + AQ_L + so) = *(const uint4*)(Ql + g);
    }
    load_kv(0, 0);
    __syncthreads();

    uint32_t aqh[4][4];
#pragma unroll
    for (int ki = 0; ki < 4; ki++)
        ldsm4(aqh[ki], addrA_s(sb + AQ_H, wid * 16, ki * 16, lane, STR));

    float cacc[8][4];
#pragma unroll
    for (int nj = 0; nj < 8; nj++)
#pragma unroll
        for (int e = 0; e < 4; e++) cacc[nj][e] = 0.f;
    float m0 = -1e30f, m1 = -1e30f, l0 = 0.f, l1 = 0.f;

    for (int kt = 0; kt < 32; kt++) {
        const int s = kt & 1;
        CP_WAIT0();
        __syncthreads();
        if (kt < 31) load_kv(kt + 1, s ^ 1);

        uint32_t base = sb + A_KV0 + s * AST;

        // S = Q @ K^T
        float sacc[8][4];
#pragma unroll
        for (int nj = 0; nj < 8; nj++)
#pragma unroll
            for (int e = 0; e < 4; e++) sacc[nj][e] = 0.f;
#pragma unroll
        for (int ki = 0; ki < 4; ki++) {
            uint32_t aql[4];
            ldsm4(aql, addrA_s(sb + AQ_L, wid * 16, ki * 16, lane, STR));
#pragma unroll
            for (int p = 0; p < 4; p++) {
                uint32_t kh2[4], kl2[4];
                ldsm4(kh2, addrB_s(base + A_KH, p * 16, ki * 16, lane, STR));
                ldsm4(kl2, addrB_s(base + A_KL, p * 16, ki * 16, lane, STR));
#pragma unroll
                for (int q = 0; q < 2; q++) {
                    int nj = 2 * p + q;
                    mma16816(sacc[nj], aqh[ki], &kh2[q * 2], sacc[nj]);
                    mma16816(sacc[nj], aql,     &kh2[q * 2], sacc[nj]);
                    mma16816(sacc[nj], aqh[ki], &kl2[q * 2], sacc[nj]);
                }
            }
        }

        // register softmax: rows r=lane>>2 (m0/l0) and r+8 (m1/l1)
        float mx0 = -1e30f, mx1 = -1e30f;
#pragma unroll
        for (int nj = 0; nj < 8; nj++) {
            mx0 = fmaxf(mx0, fmaxf(sacc[nj][0], sacc[nj][1]));
            mx1 = fmaxf(mx1, fmaxf(sacc[nj][2], sacc[nj][3]));
        }
        mx0 = fmaxf(mx0, __shfl_xor_sync(0xffffffffu, mx0, 1));
        mx0 = fmaxf(mx0, __shfl_xor_sync(0xffffffffu, mx0, 2));
        mx1 = fmaxf(mx1, __shfl_xor_sync(0xffffffffu, mx1, 1));
        mx1 = fmaxf(mx1, __shfl_xor_sync(0xffffffffu, mx1, 2));
        float mn0 = fmaxf(m0, mx0), mn1 = fmaxf(m1, mx1);
        float c0 = __expf(m0 - mn0), c1 = __expf(m1 - mn1);
        m0 = mn0; m1 = mn1;

        uint32_t aPh[4][4], aPl[4][4];
        float ls0 = 0.f, ls1 = 0.f;
#pragma unroll
        for (int ki = 0; ki < 4; ki++) {
#pragma unroll
            for (int jj = 0; jj < 2; jj++) {
                int nj = 2 * ki + jj;
                float p0 = __expf(sacc[nj][0] - mn0);
                float p1 = __expf(sacc[nj][1] - mn0);
                float p2 = __expf(sacc[nj][2] - mn1);
                float p3 = __expf(sacc[nj][3] - mn1);
                ls0 += p0 + p1; ls1 += p2 + p3;
                aPh[ki][2 * jj + 0] = splitpack(p0, p1);
                aPh[ki][2 * jj + 1] = splitpack(p2, p3);
                aPl[ki][2 * jj + 0] = splitpack_lo(p0, p1);
                aPl[ki][2 * jj + 1] = splitpack_lo(p2, p3);
            }
        }
        ls0 += __shfl_xor_sync(0xffffffffu, ls0, 1);
        ls0 += __shfl_xor_sync(0xffffffffu, ls0, 2);
        ls1 += __shfl_xor_sync(0xffffffffu, ls1, 1);
        ls1 += __shfl_xor_sync(0xffffffffu, ls1, 2);
        l0 = l0 * c0 + ls0;
        l1 = l1 * c1 + ls1;

#pragma unroll
        for (int nj = 0; nj < 8; nj++) {
            cacc[nj][0] *= c0; cacc[nj][1] *= c0;
            cacc[nj][2] *= c1; cacc[nj][3] *= c1;
        }

        // PV
#pragma unroll
        for (int ki = 0; ki < 4; ki++) {
#pragma unroll
            for (int p = 0; p < 4; p++) {
                uint32_t vh2[4], vl2[4];
                ldsm4t(vh2, addrV_s(base + A_VH, ki * 16, p * 16, lane, STR));
                ldsm4t(vl2, addrV_s(base + A_VL, ki * 16, p * 16, lane, STR));
#pragma unroll
                for (int q = 0; q < 2; q++) {
                    int nj = 2 * p + q;
                    mma16816(cacc[nj], aPh[ki], &vh2[q * 2], cacc[nj]);
                    mma16816(cacc[nj], aPl[ki], &vh2[q * 2], cacc[nj]);
                    mma16816(cacc[nj], aPh[ki], &vl2[q * 2], cacc[nj]);
                }
            }
        }
    }

    float inv0 = 1.0f / (8.0f * l0);   // post-softmax /sqrt(d) quirk
    float inv1 = 1.0f / (8.0f * l1);
    {
        int r = wid * 16 + (lane >> 2);
        size_t grow = (size_t)bh * SEQ + q0 + r;
#pragma unroll
        for (int nj = 0; nj < 8; nj++) {
            int col = nj * 8 + 2 * (lane & 3);
            float a0 = cacc[nj][0] * inv0, a1 = cacc[nj][1] * inv0;
            float a2 = cacc[nj][2] * inv1, a3 = cacc[nj][3] * inv1;
            *(uint32_t*)&g_Chi[grow * DPH + col]       = splitpack(a0, a1);
            *(uint32_t*)&g_Clo[grow * DPH + col]       = splitpack_lo(a0, a1);
            *(uint32_t*)&g_Chi[(grow + 8) * DPH + col] = splitpack(a2, a3);
            *(uint32_t*)&g_Clo[(grow + 8) * DPH + col] = splitpack_lo(a2, a3);
        }
    }
}

// ---------------------------------------------------------------------------
// Kernel 3: output projection: ctx[32768,64] @ Wo[64,1024] + bo
// Block 128x128, 8 warps, single K chunk of 64, 2 CTAs/SM.
// ---------------------------------------------------------------------------
#define O_AH 0
#define O_AL 18432
#define O_BH 36864
#define O_BL 55296
#define O_SMEM 73728

__global__ __launch_bounds__(256, 2) void outproj_mma(const float* __restrict__ bo,
                                                      float* __restrict__ out) {
    extern __shared__ char sm[];
    uint32_t sb = smem_u32(sm);
    const int m0 = blockIdx.y * 128;
    const int n0 = blockIdx.x * 128;
    const int tid = threadIdx.x, wid = tid >> 5, lane = tid & 31;
    const int wm = (wid >> 2) * 64;
    const int wn = (wid & 3) * 32;

#pragma unroll
    for (int i = 0; i < 4; i++) {
        int idx = i * 256 + tid;
        int row = idx >> 3, v = idx & 7;
        uint32_t so = (uint32_t)(row * STR + v * 8) * 2;
        size_t gA = (size_t)(m0 + row) * DPH + v * 8;
        size_t gB = (size_t)(n0 + row) * DPH + v * 8;
        CP_A16(sb + O_AH + so, g_Chi + gA);
        CP_A16(sb + O_AL + so, g_Clo + gA);
        CP_A16(sb + O_BH + so, g_Wothi + gB);
        CP_A16(sb + O_BL + so, g_Wotlo + gB);
    }
    CP_COMMIT();
    CP_WAIT0();
    __syncthreads();

    float acc[4][4][4];
#pragma unroll
    for (int mi = 0; mi < 4; mi++)
#pragma unroll
        for (int nj = 0; nj < 4; nj++)
#pragma unroll
            for (int e = 0; e < 4; e++) acc[mi][nj][e] = 0.f;

#pragma unroll
    for (int ki = 0; ki < 4; ki++) {
        uint32_t bh[2][4], bl[2][4];
#pragma unroll
        for (int p = 0; p < 2; p++) {
            ldsm4(bh[p], addrB_s(sb + O_BH, wn + p * 16, ki * 16, lane, STR));
            ldsm4(bl[p], addrB_s(sb + O_BL, wn + p * 16, ki * 16, lane, STR));
        }
#pragma unroll
        for (int mi = 0; mi < 4; mi++) {
            uint32_t ah[4], al[4];
            ldsm4(ah, addrA_s(sb + O_AH, wm + mi * 16, ki * 16, lane, STR));
            ldsm4(al, addrA_s(sb + O_AL, wm + mi * 16, ki * 16, lane, STR));
#pragma unroll
            for (int nj = 0; nj < 4; nj++) {
                const uint32_t* bhp = &bh[nj >> 1][(nj & 1) * 2];
                const uint32_t* blp = &bl[nj >> 1][(nj & 1) * 2];
                mma16816(acc[mi][nj], ah, bhp, acc[mi][nj]);
                mma16816(acc[mi][nj], al, bhp, acc[mi][nj]);
                mma16816(acc[mi][nj], ah, blp, acc[mi][nj]);
            }
        }
    }

#pragma unroll
    for (int mi = 0; mi < 4; mi++) {
#pragma unroll
        for (int nj = 0; nj < 4; nj++) {
            int row = m0 + wm + mi * 16 + (lane >> 2);
            int col = n0 + wn + nj * 8 + 2 * (lane & 3);
            float2 bv = *(const float2*)&bo[col];
            *(float2*)&out[(size_t)row * OUTF + col] =
                make_float2(acc[mi][nj][0] + bv.x, acc[mi][nj][1] + bv.y);
            *(float2*)&out[(size_t)(row + 8) * OUTF + col] =
                make_float2(acc[mi][nj][2] + bv.x, acc[mi][nj][3] + bv.y);
        }
    }
}

// ---------------------------------------------------------------------------
extern "C" void kernel_launch(void* const* d_in, const int* in_sizes, int n_in,
                              void* d_out, int out_size)
{
    const float* inputs = (const float*)d_in[0];
    const float* Wq     = (const float*)d_in[1];
    const float* Wk     = (const float*)d_in[2];
    const float* Wv     = (const float*)d_in[3];
    const float* Wo     = (const float*)d_in[4];
    const float* bo     = (const float*)d_in[5];
    float* out = (float*)d_out;

    cudaFuncSetAttribute(qkv_mma, cudaFuncAttributeMaxDynamicSharedMemorySize, QG_SMEM);
    cudaFuncSetAttribute(attn_fa2, cudaFuncAttributeMaxDynamicSharedMemorySize, AT_SMEM);
    cudaFuncSetAttribute(outproj_mma, cudaFuncAttributeMaxDynamicSharedMemorySize, O_SMEM);

    prep_split_A<<<(MROWS * INF / 4) / 256, 256>>>(inputs);
    {
        dim3 grid(INF / 32, NP / 32, 3);
        prep_Wt<<<grid, dim3(32, 8)>>>(Wq, Wk, Wv);
    }
    {
        dim3 grid(DPH / 32, OUTF / 32);
        prep_Wot<<<grid, dim3(32, 8)>>>(Wo);
    }
    {
        dim3 grid(NP / 128, MROWS / 128, 3);
        qkv_mma<<<grid, 256, QG_SMEM>>>();
    }
    {
        dim3 grid(SEQ / 128, BATCH * HEADS);
        attn_fa2<<<grid, 256, AT_SMEM>>>();
    }
    {
        dim3 grid(OUTF / 128, CTXROWS / 128);
        outproj_mma<<<grid, 256, O_SMEM>>>(bo, out);
    }
}

// round 6
// speedup vs baseline: 3.8319x; 1.1494x over previous
#include <cuda_runtime.h>
#include <cuda_bf16.h>
#include <cuda_fp16.h>
#include <cstdint>

// ---------------------------------------------------------------------------
// Problem constants
// ---------------------------------------------------------------------------
#define BATCH 2
#define SEQ   2048
#define INF   1024
#define HEADS 8
#define DPH   64
#define OUTF  1024
#define NP    512                 // HEADS*DPH
#define MROWS (BATCH*SEQ)         // 4096
#define PSZ   (MROWS*NP)          // elems per projection
#define CTXROWS (BATCH*HEADS*SEQ) // 32768

// Scratch (module-static device memory; no runtime allocation)
__device__ __nv_bfloat16 g_Ahi[MROWS * INF];
__device__ __nv_bfloat16 g_Alo[MROWS * INF];
__device__ __nv_bfloat16 g_Wthi[3 * NP * INF];    // W^T split hi [n][k]
__device__ __nv_bfloat16 g_Wtlo[3 * NP * INF];
__device__ __nv_bfloat16 g_Wothi[OUTF * DPH];     // Wo^T split hi [n][k]
__device__ __nv_bfloat16 g_Wotlo[OUTF * DPH];
__device__ __nv_bfloat16 g_Phi[2 * PSZ];          // Q,K split hi
__device__ __nv_bfloat16 g_Plo[2 * PSZ];          // Q,K split lo
__device__ __half        g_Vfp[PSZ];              // V single fp16
__device__ __nv_bfloat16 g_Chi[CTXROWS * DPH];    // ctx split hi
__device__ __nv_bfloat16 g_Clo[CTXROWS * DPH];

// ---------------------------------------------------------------------------
// Helpers
// ---------------------------------------------------------------------------
__device__ __forceinline__ uint32_t smem_u32(const void* p) {
    uint32_t a;
    asm("{ .reg .u64 t; cvta.to.shared.u64 t, %1; cvt.u32.u64 %0, t; }"
        : "=r"(a) : "l"(p));
    return a;
}

__device__ __forceinline__ void mma16816(float d[4], const uint32_t a[4],
                                         const uint32_t b[2], const float c[4]) {
    asm volatile(
        "mma.sync.aligned.m16n8k16.row.col.f32.bf16.bf16.f32 "
        "{%0,%1,%2,%3}, {%4,%5,%6,%7}, {%8,%9}, {%10,%11,%12,%13};"
        : "=f"(d[0]), "=f"(d[1]), "=f"(d[2]), "=f"(d[3])
        : "r"(a[0]), "r"(a[1]), "r"(a[2]), "r"(a[3]),
          "r"(b[0]), "r"(b[1]),
          "f"(c[0]), "f"(c[1]), "f"(c[2]), "f"(c[3]));
}
__device__ __forceinline__ void mma16816h(float d[4], const uint32_t a[4],
                                          const uint32_t b[2], const float c[4]) {
    asm volatile(
        "mma.sync.aligned.m16n8k16.row.col.f32.f16.f16.f32 "
        "{%0,%1,%2,%3}, {%4,%5,%6,%7}, {%8,%9}, {%10,%11,%12,%13};"
        : "=f"(d[0]), "=f"(d[1]), "=f"(d[2]), "=f"(d[3])
        : "r"(a[0]), "r"(a[1]), "r"(a[2]), "r"(a[3]),
          "r"(b[0]), "r"(b[1]),
          "f"(c[0]), "f"(c[1]), "f"(c[2]), "f"(c[3]));
}

__device__ __forceinline__ void ldsm4(uint32_t r[4], uint32_t addr) {
    asm volatile("ldmatrix.sync.aligned.m8n8.x4.shared.b16 {%0,%1,%2,%3}, [%4];"
                 : "=r"(r[0]), "=r"(r[1]), "=r"(r[2]), "=r"(r[3]) : "r"(addr));
}
__device__ __forceinline__ void ldsm4t(uint32_t r[4], uint32_t addr) {
    asm volatile("ldmatrix.sync.aligned.m8n8.x4.trans.shared.b16 {%0,%1,%2,%3}, [%4];"
                 : "=r"(r[0]), "=r"(r[1]), "=r"(r[2]), "=r"(r[3]) : "r"(addr));
}

#define CP_A16(dst, src) \
    asm volatile("cp.async.cg.shared.global [%0], [%1], 16;" :: "r"(dst), "l"(src) : "memory")
#define CP_COMMIT() asm volatile("cp.async.commit_group;" ::: "memory")
#define CP_WAIT0()  asm volatile("cp.async.wait_group 0;" ::: "memory")

__device__ __forceinline__ void split1(float v, __nv_bfloat16& h, __nv_bfloat16& l) {
    h = __float2bfloat16_rn(v);
    l = __float2bfloat16_rn(v - __bfloat162float(h));
}
__device__ __forceinline__ uint32_t pack2(__nv_bfloat16 a, __nv_bfloat16 b) {
    __nv_bfloat162 p = __halves2bfloat162(a, b);
    return *reinterpret_cast<uint32_t*>(&p);
}
__device__ __forceinline__ uint2 pack4(__nv_bfloat16 a, __nv_bfloat16 b,
                                       __nv_bfloat16 c, __nv_bfloat16 d) {
    uint2 r; r.x = pack2(a, b); r.y = pack2(c, d); return r;
}
__device__ __forceinline__ uint32_t splitpack(float a, float b) {
    __nv_bfloat16 h0, l0, h1, l1;
    split1(a, h0, l0); split1(b, h1, l1);
    return pack2(h0, h1);
}
__device__ __forceinline__ uint32_t splitpack_lo(float a, float b) {
    __nv_bfloat16 h0, l0, h1, l1;
    split1(a, h0, l0); split1(b, h1, l1);
    return pack2(l0, l1);
}
__device__ __forceinline__ uint32_t packh2(float a, float b) {
    __half2 p = __floats2half2_rn(a, b);
    return *reinterpret_cast<uint32_t*>(&p);
}

// strides (elements) for mma operand tiles in smem
#define STR  72   // 144 B rows (64-col tiles)
#define STR2 40   // 80 B rows (32-col tiles)

__device__ __forceinline__ uint32_t addrA_s(uint32_t base, int brow, int bcol, int lane, int str) {
    int row = brow + (lane & 7) + ((lane & 8) ? 8 : 0);
    int col = bcol + ((lane & 16) ? 8 : 0);
    return base + (row * str + col) * 2;
}
__device__ __forceinline__ uint32_t addrB_s(uint32_t base, int brow, int bcol, int lane, int str) {
    int row = brow + (lane & 7) + ((lane & 16) ? 8 : 0);
    int col = bcol + ((lane & 8) ? 8 : 0);
    return base + (row * str + col) * 2;
}
__device__ __forceinline__ uint32_t addrV_s(uint32_t base, int kvrow, int dcol, int lane, int str) {
    int row = kvrow + (lane & 7) + ((lane & 8) ? 8 : 0);
    int col = dcol + ((lane & 16) ? 8 : 0);
    return base + (row * str + col) * 2;
}

// ---------------------------------------------------------------------------
// Prep kernels
// ---------------------------------------------------------------------------
__global__ __launch_bounds__(256) void prep_split_A(const float* __restrict__ X) {
    int idx = blockIdx.x * blockDim.x + threadIdx.x;
    float4 v = ((const float4*)X)[idx];
    __nv_bfloat16 h0, h1, h2, h3, l0, l1, l2, l3;
    split1(v.x, h0, l0); split1(v.y, h1, l1);
    split1(v.z, h2, l2); split1(v.w, h3, l3);
    ((uint2*)g_Ahi)[idx] = pack4(h0, h1, h2, h3);
    ((uint2*)g_Alo)[idx] = pack4(l0, l1, l2, l3);
}

__global__ __launch_bounds__(256) void prep_Wt(const float* __restrict__ Wq,
                                               const float* __restrict__ Wk,
                                               const float* __restrict__ Wv) {
    const int which = blockIdx.z;
    const float* W = (which == 0) ? Wq : (which == 1) ? Wk : Wv;
    __shared__ float t[32][33];
    const int k0 = blockIdx.x * 32, n0 = blockIdx.y * 32;
    const int tx = threadIdx.x, ty = threadIdx.y;
#pragma unroll
    for (int j = 0; j < 4; j++)
        t[ty + j * 8][tx] = W[(size_t)(k0 + ty + j * 8) * NP + n0 + tx];
    __syncthreads();
#pragma unroll
    for (int j = 0; j < 4; j++) {
        int n = n0 + ty + j * 8, k = k0 + tx;
        float v = t[tx][ty + j * 8];
        __nv_bfloat16 h, l; split1(v, h, l);
        size_t o = ((size_t)which * NP + n) * INF + k;
        g_Wthi[o] = h; g_Wtlo[o] = l;
    }
}

__global__ __launch_bounds__(256) void prep_Wot(const float* __restrict__ Wo) {
    __shared__ float t[32][33];
    const int k0 = blockIdx.x * 32, n0 = blockIdx.y * 32;
    const int tx = threadIdx.x, ty = threadIdx.y;
#pragma unroll
    for (int j = 0; j < 4; j++)
        t[ty + j * 8][tx] = Wo[(size_t)(k0 + ty + j * 8) * OUTF + n0 + tx];
    __syncthreads();
#pragma unroll
    for (int j = 0; j < 4; j++) {
        int n = n0 + ty + j * 8, k = k0 + tx;
        float v = t[tx][ty + j * 8];
        __nv_bfloat16 h, l; split1(v, h, l);
        size_t o = (size_t)n * DPH + k;
        g_Wothi[o] = h; g_Wotlo[o] = l;
    }
}

// ---------------------------------------------------------------------------
// Kernel 1: QKV projection. Block 128x128, 8 warps, K chunks of 32, 2 stages.
// Q,K epilogue -> bf16 hi/lo; V epilogue -> fp16 single.
// ---------------------------------------------------------------------------
#define Q2_MAT (128*STR2*2)        // 10240 per matrix
#define Q2_AH 0
#define Q2_AL Q2_MAT
#define Q2_BH (2*Q2_MAT)
#define Q2_BL (3*Q2_MAT)
#define Q2ST  (4*Q2_MAT)           // 40960 stage stride
#define QG_SMEM (2*Q2ST)           // 81920

__global__ __launch_bounds__(256, 2) void qkv_mma() {
    extern __shared__ char sm[];
    uint32_t sb = smem_u32(sm);
    const int which = blockIdx.z;
    const int m0 = blockIdx.y * 128;
    const int n0 = blockIdx.x * 128;
    const int tid = threadIdx.x, wid = tid >> 5, lane = tid & 31;
    const int wm = (wid >> 2) * 64;
    const int wn = (wid & 3) * 32;

    const __nv_bfloat16* Bh = g_Wthi + (size_t)which * NP * INF;
    const __nv_bfloat16* Bl = g_Wtlo + (size_t)which * NP * INF;

    float acc[4][4][4];
#pragma unroll
    for (int mi = 0; mi < 4; mi++)
#pragma unroll
        for (int nj = 0; nj < 4; nj++)
#pragma unroll
            for (int e = 0; e < 4; e++) acc[mi][nj][e] = 0.f;

    auto load_chunk = [&](int c, int stage) {
        uint32_t base = sb + stage * Q2ST;
        const int k0 = c * 32;
#pragma unroll
        for (int i = 0; i < 2; i++) {
            int idx = i * 256 + tid;
            int row = idx >> 2, v = idx & 3;
            uint32_t so = (uint32_t)(row * STR2 + v * 8) * 2;
            size_t gA = (size_t)(m0 + row) * INF + k0 + v * 8;
            size_t gB = (size_t)(n0 + row) * INF + k0 + v * 8;
            CP_A16(base + Q2_AH + so, g_Ahi + gA);
            CP_A16(base + Q2_AL + so, g_Alo + gA);
            CP_A16(base + Q2_BH + so, Bh + gB);
            CP_A16(base + Q2_BL + so, Bl + gB);
        }
        CP_COMMIT();
    };

    load_chunk(0, 0);

    for (int c = 0; c < 32; ++c) {
        const int s = c & 1;
        CP_WAIT0();
        __syncthreads();
        if (c < 31) load_chunk(c + 1, s ^ 1);

        uint32_t base = sb + s * Q2ST;
#pragma unroll
        for (int ki = 0; ki < 2; ki++) {
            uint32_t bh[2][4], bl[2][4];
#pragma unroll
            for (int p = 0; p < 2; p++) {
                ldsm4(bh[p], addrB_s(base + Q2_BH, wn + p * 16, ki * 16, lane, STR2));
                ldsm4(bl[p], addrB_s(base + Q2_BL, wn + p * 16, ki * 16, lane, STR2));
            }
#pragma unroll
            for (int mi = 0; mi < 4; mi++) {
                uint32_t ah[4], al[4];
                ldsm4(ah, addrA_s(base + Q2_AH, wm + mi * 16, ki * 16, lane, STR2));
                ldsm4(al, addrA_s(base + Q2_AL, wm + mi * 16, ki * 16, lane, STR2));
#pragma unroll
                for (int nj = 0; nj < 4; nj++) {
                    const uint32_t* bhp = &bh[nj >> 1][(nj & 1) * 2];
                    const uint32_t* blp = &bl[nj >> 1][(nj & 1) * 2];
                    mma16816(acc[mi][nj], ah, bhp, acc[mi][nj]);
                    mma16816(acc[mi][nj], al, bhp, acc[mi][nj]);
                    mma16816(acc[mi][nj], ah, blp, acc[mi][nj]);
                }
            }
        }
    }

    if (which < 2) {
        __nv_bfloat16* Ph = g_Phi + (size_t)which * PSZ;
        __nv_bfloat16* Pl = g_Plo + (size_t)which * PSZ;
#pragma unroll
        for (int mi = 0; mi < 4; mi++) {
#pragma unroll
            for (int nj = 0; nj < 4; nj++) {
                int row = m0 + wm + mi * 16 + (lane >> 2);
                int col = n0 + wn + nj * 8 + 2 * (lane & 3);
                *(uint32_t*)&Ph[(size_t)row * NP + col] = splitpack(acc[mi][nj][0], acc[mi][nj][1]);
                *(uint32_t*)&Pl[(size_t)row * NP + col] = splitpack_lo(acc[mi][nj][0], acc[mi][nj][1]);
                *(uint32_t*)&Ph[(size_t)(row + 8) * NP + col] = splitpack(acc[mi][nj][2], acc[mi][nj][3]);
                *(uint32_t*)&Pl[(size_t)(row + 8) * NP + col] = splitpack_lo(acc[mi][nj][2], acc[mi][nj][3]);
            }
        }
    } else {
        // V: single fp16
#pragma unroll
        for (int mi = 0; mi < 4; mi++) {
#pragma unroll
            for (int nj = 0; nj < 4; nj++) {
                int row = m0 + wm + mi * 16 + (lane >> 2);
                int col = n0 + wn + nj * 8 + 2 * (lane & 3);
                *(uint32_t*)&g_Vfp[(size_t)row * NP + col]       = packh2(acc[mi][nj][0], acc[mi][nj][1]);
                *(uint32_t*)&g_Vfp[(size_t)(row + 8) * NP + col] = packh2(acc[mi][nj][2], acc[mi][nj][3]);
            }
        }
    }
}

// ---------------------------------------------------------------------------
// Kernel 2: FA2 flash attention. 128 q-rows, 256 threads, KV chunks of 64
// double-buffered. QK: 3-term split bf16. PV: single fp16 MMA (P fp16, V fp16).
// ---------------------------------------------------------------------------
#define AQ_H 0
#define AQ_L 18432
#define A_KV0 36864                 // KV stages base
#define A_KH 0
#define A_KL 9216
#define A_VF 18432
#define AST  27648                  // stage stride (KH,KL bf16 + V fp16)
#define AT_SMEM (A_KV0 + 2*AST)     // 92160

__global__ __launch_bounds__(256, 2) void attn_fa2() {
    extern __shared__ char sm[];
    uint32_t sb = smem_u32(sm);
    const int bh = blockIdx.y;
    const int b = bh >> 3, h = bh & 7;
    const size_t hoff = ((size_t)b * SEQ + (size_t)h * 256) * NP;
    const __nv_bfloat16* Qh = g_Phi + hoff;
    const __nv_bfloat16* Ql = g_Plo + hoff;
    const __nv_bfloat16* Kh = g_Phi + PSZ + hoff;
    const __nv_bfloat16* Kl = g_Plo + PSZ + hoff;
    const __half*        Vf = g_Vfp + hoff;

    const int q0 = blockIdx.x * 128;
    const int tid = threadIdx.x, wid = tid >> 5, lane = tid & 31;

    auto load_kv = [&](int kt, int stage) {
        uint32_t base = sb + A_KV0 + stage * AST;
#pragma unroll
        for (int i = 0; i < 2; i++) {
            int idx = i * 256 + tid;
            int row = idx >> 3, v = idx & 7;
            uint32_t so = (uint32_t)(row * STR + v * 8) * 2;
            size_t g = (size_t)(kt * 64 + row) * DPH + v * 8;
            CP_A16(base + A_KH + so, Kh + g);
            CP_A16(base + A_KL + so, Kl + g);
            CP_A16(base + A_VF + so, Vf + g);
        }
        CP_COMMIT();
    };

    // Persistent Q region (hi + lo)
#pragma unroll
    for (int i = 0; i < 4; i++) {
        int idx = i * 256 + tid;
        int row = idx >> 3, v = idx & 7;
        uint32_t so = (uint32_t)(row * STR + v * 8) * 2;
        size_t g = (size_t)(q0 + row) * DPH + v * 8;
        *(uint4*)(sm + AQ_H + so) = *(const uint4*)(Qh + g);
        *(uint4*)(sm + AQ_L + so) = *(const uint4*)(Ql + g);
    }
    load_kv(0, 0);
    __syncthreads();

    uint32_t aqh[4][4];
#pragma unroll
    for (int ki = 0; ki < 4; ki++)
        ldsm4(aqh[ki], addrA_s(sb + AQ_H, wid * 16, ki * 16, lane, STR));

    float cacc[8][4];
#pragma unroll
    for (int nj = 0; nj < 8; nj++)
#pragma unroll
        for (int e = 0; e < 4; e++) cacc[nj][e] = 0.f;
    float m0 = -1e30f, m1 = -1e30f, l0 = 0.f, l1 = 0.f;

    for (int kt = 0; kt < 32; kt++) {
        const int s = kt & 1;
        CP_WAIT0();
        __syncthreads();
        if (kt < 31) load_kv(kt + 1, s ^ 1);

        uint32_t base = sb + A_KV0 + s * AST;

        // S = Q @ K^T (3-term split)
        float sacc[8][4];
#pragma unroll
        for (int nj = 0; nj < 8; nj++)
#pragma unroll
            for (int e = 0; e < 4; e++) sacc[nj][e] = 0.f;
#pragma unroll
        for (int ki = 0; ki < 4; ki++) {
            uint32_t aql[4];
            ldsm4(aql, addrA_s(sb + AQ_L, wid * 16, ki * 16, lane, STR));
#pragma unroll
            for (int p = 0; p < 4; p++) {
                uint32_t kh2[4], kl2[4];
                ldsm4(kh2, addrB_s(base + A_KH, p * 16, ki * 16, lane, STR));
                ldsm4(kl2, addrB_s(base + A_KL, p * 16, ki * 16, lane, STR));
#pragma unroll
                for (int q = 0; q < 2; q++) {
                    int nj = 2 * p + q;
                    mma16816(sacc[nj], aqh[ki], &kh2[q * 2], sacc[nj]);
                    mma16816(sacc[nj], aql,     &kh2[q * 2], sacc[nj]);
                    mma16816(sacc[nj], aqh[ki], &kl2[q * 2], sacc[nj]);
                }
            }
        }

        // register softmax: rows r=lane>>2 (m0/l0) and r+8 (m1/l1)
        float mx0 = -1e30f, mx1 = -1e30f;
#pragma unroll
        for (int nj = 0; nj < 8; nj++) {
            mx0 = fmaxf(mx0, fmaxf(sacc[nj][0], sacc[nj][1]));
            mx1 = fmaxf(mx1, fmaxf(sacc[nj][2], sacc[nj][3]));
        }
        mx0 = fmaxf(mx0, __shfl_xor_sync(0xffffffffu, mx0, 1));
        mx0 = fmaxf(mx0, __shfl_xor_sync(0xffffffffu, mx0, 2));
        mx1 = fmaxf(mx1, __shfl_xor_sync(0xffffffffu, mx1, 1));
        mx1 = fmaxf(mx1, __shfl_xor_sync(0xffffffffu, mx1, 2));
        float mn0 = fmaxf(m0, mx0), mn1 = fmaxf(m1, mx1);
        float c0 = __expf(m0 - mn0), c1 = __expf(m1 - mn1);
        m0 = mn0; m1 = mn1;

        // P as fp16 A-fragments (C-frag layout == A-frag layout)
        uint32_t aP[4][4];
        float ls0 = 0.f, ls1 = 0.f;
#pragma unroll
        for (int ki = 0; ki < 4; ki++) {
#pragma unroll
            for (int jj = 0; jj < 2; jj++) {
                int nj = 2 * ki + jj;
                float p0 = __expf(sacc[nj][0] - mn0);
                float p1 = __expf(sacc[nj][1] - mn0);
                float p2 = __expf(sacc[nj][2] - mn1);
                float p3 = __expf(sacc[nj][3] - mn1);
                ls0 += p0 + p1; ls1 += p2 + p3;
                aP[ki][2 * jj + 0] = packh2(p0, p1);
                aP[ki][2 * jj + 1] = packh2(p2, p3);
            }
        }
        ls0 += __shfl_xor_sync(0xffffffffu, ls0, 1);
        ls0 += __shfl_xor_sync(0xffffffffu, ls0, 2);
        ls1 += __shfl_xor_sync(0xffffffffu, ls1, 1);
        ls1 += __shfl_xor_sync(0xffffffffu, ls1, 2);
        l0 = l0 * c0 + ls0;
        l1 = l1 * c1 + ls1;

#pragma unroll
        for (int nj = 0; nj < 8; nj++) {
            cacc[nj][0] *= c0; cacc[nj][1] *= c0;
            cacc[nj][2] *= c1; cacc[nj][3] *= c1;
        }

        // PV: single fp16 MMA per tile
#pragma unroll
        for (int ki = 0; ki < 4; ki++) {
#pragma unroll
            for (int p = 0; p < 4; p++) {
                uint32_t v2[4];
                ldsm4t(v2, addrV_s(base + A_VF, ki * 16, p * 16, lane, STR));
#pragma unroll
                for (int q = 0; q < 2; q++) {
                    int nj = 2 * p + q;
                    mma16816h(cacc[nj], aP[ki], &v2[q * 2], cacc[nj]);
                }
            }
        }
    }

    float inv0 = 1.0f / (8.0f * l0);   // post-softmax /sqrt(d) quirk
    float inv1 = 1.0f / (8.0f * l1);
    {
        int r = wid * 16 + (lane >> 2);
        size_t grow = (size_t)bh * SEQ + q0 + r;
#pragma unroll
        for (int nj = 0; nj < 8; nj++) {
            int col = nj * 8 + 2 * (lane & 3);
            float a0 = cacc[nj][0] * inv0, a1 = cacc[nj][1] * inv0;
            float a2 = cacc[nj][2] * inv1, a3 = cacc[nj][3] * inv1;
            *(uint32_t*)&g_Chi[grow * DPH + col]       = splitpack(a0, a1);
            *(uint32_t*)&g_Clo[grow * DPH + col]       = splitpack_lo(a0, a1);
            *(uint32_t*)&g_Chi[(grow + 8) * DPH + col] = splitpack(a2, a3);
            *(uint32_t*)&g_Clo[(grow + 8) * DPH + col] = splitpack_lo(a2, a3);
        }
    }
}

// ---------------------------------------------------------------------------
// Kernel 3: output projection: ctx[32768,64] @ Wo[64,1024] + bo
// Block 128x128, 8 warps, single K chunk of 64, 2 CTAs/SM.
// ---------------------------------------------------------------------------
#define O_AH 0
#define O_AL 18432
#define O_BH 36864
#define O_BL 55296
#define O_SMEM 73728

__global__ __launch_bounds__(256, 2) void outproj_mma(const float* __restrict__ bo,
                                                      float* __restrict__ out) {
    extern __shared__ char sm[];
    uint32_t sb = smem_u32(sm);
    const int m0 = blockIdx.y * 128;
    const int n0 = blockIdx.x * 128;
    const int tid = threadIdx.x, wid = tid >> 5, lane = tid & 31;
    const int wm = (wid >> 2) * 64;
    const int wn = (wid & 3) * 32;

#pragma unroll
    for (int i = 0; i < 4; i++) {
        int idx = i * 256 + tid;
        int row = idx >> 3, v = idx & 7;
        uint32_t so = (uint32_t)(row * STR + v * 8) * 2;
        size_t gA = (size_t)(m0 + row) * DPH + v * 8;
        size_t gB = (size_t)(n0 + row) * DPH + v * 8;
        CP_A16(sb + O_AH + so, g_Chi + gA);
        CP_A16(sb + O_AL + so, g_Clo + gA);
        CP_A16(sb + O_BH + so, g_Wothi + gB);
        CP_A16(sb + O_BL + so, g_Wotlo + gB);
    }
    CP_COMMIT();
    CP_WAIT0();
    __syncthreads();

    float acc[4][4][4];
#pragma unroll
    for (int mi = 0; mi < 4; mi++)
#pragma unroll
        for (int nj = 0; nj < 4; nj++)
#pragma unroll
            for (int e = 0; e < 4; e++) acc[mi][nj][e] = 0.f;

#pragma unroll
    for (int ki = 0; ki < 4; ki++) {
        uint32_t bh[2][4], bl[2][4];
#pragma unroll
        for (int p = 0; p < 2; p++) {
            ldsm4(bh[p], addrB_s(sb + O_BH, wn + p * 16, ki * 16, lane, STR));
            ldsm4(bl[p], addrB_s(sb + O_BL, wn + p * 16, ki * 16, lane, STR));
        }
#pragma unroll
        for (int mi = 0; mi < 4; mi++) {
            uint32_t ah[4], al[4];
            ldsm4(ah, addrA_s(sb + O_AH, wm + mi * 16, ki * 16, lane, STR));
            ldsm4(al, addrA_s(sb + O_AL, wm + mi * 16, ki * 16, lane, STR));
#pragma unroll
            for (int nj = 0; nj < 4; nj++) {
                const uint32_t* bhp = &bh[nj >> 1][(nj & 1) * 2];
                const uint32_t* blp = &bl[nj >> 1][(nj & 1) * 2];
                mma16816(acc[mi][nj], ah, bhp, acc[mi][nj]);
                mma16816(acc[mi][nj], al, bhp, acc[mi][nj]);
                mma16816(acc[mi][nj], ah, blp, acc[mi][nj]);
            }
        }
    }

#pragma unroll
    for (int mi = 0; mi < 4; mi++) {
#pragma unroll
        for (int nj = 0; nj < 4; nj++) {
            int row = m0 + wm + mi * 16 + (lane >> 2);
            int col = n0 + wn + nj * 8 + 2 * (lane & 3);
            float2 bv = *(const float2*)&bo[col];
            *(float2*)&out[(size_t)row * OUTF + col] =
                make_float2(acc[mi][nj][0] + bv.x, acc[mi][nj][1] + bv.y);
            *(float2*)&out[(size_t)(row + 8) * OUTF + col] =
                make_float2(acc[mi][nj][2] + bv.x, acc[mi][nj][3] + bv.y);
        }
    }
}

// ---------------------------------------------------------------------------
extern "C" void kernel_launch(void* const* d_in, const int* in_sizes, int n_in,
                              void* d_out, int out_size)
{
    const float* inputs = (const float*)d_in[0];
    const float* Wq     = (const float*)d_in[1];
    const float* Wk     = (const float*)d_in[2];
    const float* Wv     = (const float*)d_in[3];
    const float* Wo     = (const float*)d_in[4];
    const float* bo     = (const float*)d_in[5];
    float* out = (float*)d_out;

    cudaFuncSetAttribute(qkv_mma, cudaFuncAttributeMaxDynamicSharedMemorySize, QG_SMEM);
    cudaFuncSetAttribute(attn_fa2, cudaFuncAttributeMaxDynamicSharedMemorySize, AT_SMEM);
    cudaFuncSetAttribute(outproj_mma, cudaFuncAttributeMaxDynamicSharedMemorySize, O_SMEM);

    prep_split_A<<<(MROWS * INF / 4) / 256, 256>>>(inputs);
    {
        dim3 grid(INF / 32, NP / 32, 3);
        prep_Wt<<<grid, dim3(32, 8)>>>(Wq, Wk, Wv);
    }
    {
        dim3 grid(DPH / 32, OUTF / 32);
        prep_Wot<<<grid, dim3(32, 8)>>>(Wo);
    }
    {
        dim3 grid(NP / 128, MROWS / 128, 3);
        qkv_mma<<<grid, 256, QG_SMEM>>>();
    }
    {
        dim3 grid(SEQ / 128, BATCH * HEADS);
        attn_fa2<<<grid, 256, AT_SMEM>>>();
    }
    {
        dim3 grid(OUTF / 128, CTXROWS / 128);
        outproj_mma<<<grid, 256, O_SMEM>>>(bo, out);
    }
}

// round 7
// speedup vs baseline: 4.8150x; 1.2566x over previous
#include <cuda_runtime.h>
#include <cuda_bf16.h>
#include <cuda_fp16.h>
#include <cstdint>

// ---------------------------------------------------------------------------
// Problem constants
// ---------------------------------------------------------------------------
#define BATCH 2
#define SEQ   2048
#define INF   1024
#define HEADS 8
#define DPH   64
#define OUTF  1024
#define NP    512                 // HEADS*DPH
#define MROWS (BATCH*SEQ)         // 4096
#define PSZ   (MROWS*NP)          // elems per projection
#define CTXROWS (BATCH*HEADS*SEQ) // 32768

// Scratch (module-static device memory; no runtime allocation)
__device__ __nv_bfloat16 g_Ahi[MROWS * INF];      // inputs bf16 hi (Q/K gemms)
__device__ __nv_bfloat16 g_Alo[MROWS * INF];      // inputs bf16 lo
__device__ __half        g_Af [MROWS * INF];      // inputs fp16 single (V gemm)
__device__ __nv_bfloat16 g_Wthi[2 * NP * INF];    // Wq,Wk ^T bf16 hi [n][k]
__device__ __nv_bfloat16 g_Wtlo[2 * NP * INF];
__device__ __half        g_Wvf[NP * INF];         // Wv^T fp16 single
__device__ __half        g_Wof[OUTF * DPH];       // Wo^T fp16 single
__device__ __half        g_Qh[PSZ];               // Q fp16 hi
__device__ __half        g_Ql[PSZ];               // Q fp16 lo
__device__ __half        g_Kf[PSZ];               // K fp16 single
__device__ __half        g_Vf[PSZ];               // V fp16 single
__device__ __half        g_Cf[CTXROWS * DPH];     // ctx fp16 single

// ---------------------------------------------------------------------------
// Helpers
// ---------------------------------------------------------------------------
__device__ __forceinline__ uint32_t smem_u32(const void* p) {
    uint32_t a;
    asm("{ .reg .u64 t; cvta.to.shared.u64 t, %1; cvt.u32.u64 %0, t; }"
        : "=r"(a) : "l"(p));
    return a;
}

__device__ __forceinline__ void mma16816(float d[4], const uint32_t a[4],
                                         const uint32_t b[2], const float c[4]) {
    asm volatile(
        "mma.sync.aligned.m16n8k16.row.col.f32.bf16.bf16.f32 "
        "{%0,%1,%2,%3}, {%4,%5,%6,%7}, {%8,%9}, {%10,%11,%12,%13};"
        : "=f"(d[0]), "=f"(d[1]), "=f"(d[2]), "=f"(d[3])
        : "r"(a[0]), "r"(a[1]), "r"(a[2]), "r"(a[3]),
          "r"(b[0]), "r"(b[1]),
          "f"(c[0]), "f"(c[1]), "f"(c[2]), "f"(c[3]));
}
__device__ __forceinline__ void mma16816h(float d[4], const uint32_t a[4],
                                          const uint32_t b[2], const float c[4]) {
    asm volatile(
        "mma.sync.aligned.m16n8k16.row.col.f32.f16.f16.f32 "
        "{%0,%1,%2,%3}, {%4,%5,%6,%7}, {%8,%9}, {%10,%11,%12,%13};"
        : "=f"(d[0]), "=f"(d[1]), "=f"(d[2]), "=f"(d[3])
        : "r"(a[0]), "r"(a[1]), "r"(a[2]), "r"(a[3]),
          "r"(b[0]), "r"(b[1]),
          "f"(c[0]), "f"(c[1]), "f"(c[2]), "f"(c[3]));
}

__device__ __forceinline__ void ldsm4(uint32_t r[4], uint32_t addr) {
    asm volatile("ldmatrix.sync.aligned.m8n8.x4.shared.b16 {%0,%1,%2,%3}, [%4];"
                 : "=r"(r[0]), "=r"(r[1]), "=r"(r[2]), "=r"(r[3]) : "r"(addr));
}
__device__ __forceinline__ void ldsm4t(uint32_t r[4], uint32_t addr) {
    asm volatile("ldmatrix.sync.aligned.m8n8.x4.trans.shared.b16 {%0,%1,%2,%3}, [%4];"
                 : "=r"(r[0]), "=r"(r[1]), "=r"(r[2]), "=r"(r[3]) : "r"(addr));
}

#define CP_A16(dst, src) \
    asm volatile("cp.async.cg.shared.global [%0], [%1], 16;" :: "r"(dst), "l"(src) : "memory")
#define CP_COMMIT() asm volatile("cp.async.commit_group;" ::: "memory")
#define CP_WAIT0()  asm volatile("cp.async.wait_group 0;" ::: "memory")

__device__ __forceinline__ void split1(float v, __nv_bfloat16& h, __nv_bfloat16& l) {
    h = __float2bfloat16_rn(v);
    l = __float2bfloat16_rn(v - __bfloat162float(h));
}
__device__ __forceinline__ void splith(float v, __half& h, __half& l) {
    h = __float2half_rn(v);
    l = __float2half_rn(v - __half2float(h));
}
__device__ __forceinline__ uint32_t pack2(__nv_bfloat16 a, __nv_bfloat16 b) {
    __nv_bfloat162 p = __halves2bfloat162(a, b);
    return *reinterpret_cast<uint32_t*>(&p);
}
__device__ __forceinline__ uint32_t pack2h(__half a, __half b) {
    __half2 p = __halves2half2(a, b);
    return *reinterpret_cast<uint32_t*>(&p);
}
__device__ __forceinline__ uint2 pack4(__nv_bfloat16 a, __nv_bfloat16 b,
                                       __nv_bfloat16 c, __nv_bfloat16 d) {
    uint2 r; r.x = pack2(a, b); r.y = pack2(c, d); return r;
}
__device__ __forceinline__ uint32_t packh2(float a, float b) {
    __half2 p = __floats2half2_rn(a, b);
    return *reinterpret_cast<uint32_t*>(&p);
}

// strides (elements) for mma operand tiles in smem
#define STR  72   // 144 B rows (64-col tiles)
#define STR2 40   // 80 B rows (32-col tiles)

__device__ __forceinline__ uint32_t addrA_s(uint32_t base, int brow, int bcol, int lane, int str) {
    int row = brow + (lane & 7) + ((lane & 8) ? 8 : 0);
    int col = bcol + ((lane & 16) ? 8 : 0);
    return base + (row * str + col) * 2;
}
__device__ __forceinline__ uint32_t addrB_s(uint32_t base, int brow, int bcol, int lane, int str) {
    int row = brow + (lane & 7) + ((lane & 16) ? 8 : 0);
    int col = bcol + ((lane & 8) ? 8 : 0);
    return base + (row * str + col) * 2;
}
__device__ __forceinline__ uint32_t addrV_s(uint32_t base, int kvrow, int dcol, int lane, int str) {
    int row = kvrow + (lane & 7) + ((lane & 8) ? 8 : 0);
    int col = dcol + ((lane & 16) ? 8 : 0);
    return base + (row * str + col) * 2;
}

// ---------------------------------------------------------------------------
// Prep kernels
// ---------------------------------------------------------------------------
__global__ __launch_bounds__(256) void prep_split_A(const float* __restrict__ X) {
    int idx = blockIdx.x * blockDim.x + threadIdx.x;
    float4 v = ((const float4*)X)[idx];
    __nv_bfloat16 h0, h1, h2, h3, l0, l1, l2, l3;
    split1(v.x, h0, l0); split1(v.y, h1, l1);
    split1(v.z, h2, l2); split1(v.w, h3, l3);
    ((uint2*)g_Ahi)[idx] = pack4(h0, h1, h2, h3);
    ((uint2*)g_Alo)[idx] = pack4(l0, l1, l2, l3);
    uint2 f; f.x = packh2(v.x, v.y); f.y = packh2(v.z, v.w);
    ((uint2*)g_Af)[idx] = f;
}

// Wq,Wk -> bf16 hi/lo transposed; Wv -> fp16 single transposed
__global__ __launch_bounds__(256) void prep_Wt(const float* __restrict__ Wq,
                                               const float* __restrict__ Wk,
                                               const float* __restrict__ Wv) {
    const int which = blockIdx.z;
    const float* W = (which == 0) ? Wq : (which == 1) ? Wk : Wv;
    __shared__ float t[32][33];
    const int k0 = blockIdx.x * 32, n0 = blockIdx.y * 32;
    const int tx = threadIdx.x, ty = threadIdx.y;
#pragma unroll
    for (int j = 0; j < 4; j++)
        t[ty + j * 8][tx] = W[(size_t)(k0 + ty + j * 8) * NP + n0 + tx];
    __syncthreads();
#pragma unroll
    for (int j = 0; j < 4; j++) {
        int n = n0 + ty + j * 8, k = k0 + tx;
        float v = t[tx][ty + j * 8];
        if (which < 2) {
            __nv_bfloat16 h, l; split1(v, h, l);
            size_t o = ((size_t)which * NP + n) * INF + k;
            g_Wthi[o] = h; g_Wtlo[o] = l;
        } else {
            g_Wvf[(size_t)n * INF + k] = __float2half_rn(v);
        }
    }
}

__global__ __launch_bounds__(256) void prep_Wo(const float* __restrict__ Wo) {
    __shared__ float t[32][33];
    const int k0 = blockIdx.x * 32, n0 = blockIdx.y * 32;
    const int tx = threadIdx.x, ty = threadIdx.y;
#pragma unroll
    for (int j = 0; j < 4; j++)
        t[ty + j * 8][tx] = Wo[(size_t)(k0 + ty + j * 8) * OUTF + n0 + tx];
    __syncthreads();
#pragma unroll
    for (int j = 0; j < 4; j++) {
        int n = n0 + ty + j * 8, k = k0 + tx;
        g_Wof[(size_t)n * DPH + k] = __float2half_rn(t[tx][ty + j * 8]);
    }
}

// ---------------------------------------------------------------------------
// Kernel 1a: Q/K projection (3-term bf16). Block 128x128, K chunks 32, 2 stg.
// Epilogue: which==0 -> Q fp16 hi/lo; which==1 -> K fp16 single.
// ---------------------------------------------------------------------------
#define Q2_MAT (128*STR2*2)        // 10240 per matrix
#define Q2_AH 0
#define Q2_AL Q2_MAT
#define Q2_BH (2*Q2_MAT)
#define Q2_BL (3*Q2_MAT)
#define Q2ST  (4*Q2_MAT)           // 40960 stage stride
#define QG_SMEM (2*Q2ST)           // 81920

__global__ __launch_bounds__(256, 2) void qk_mma() {
    extern __shared__ char sm[];
    uint32_t sb = smem_u32(sm);
    const int which = blockIdx.z;            // 0 = Q, 1 = K
    const int m0 = blockIdx.y * 128;
    const int n0 = blockIdx.x * 128;
    const int tid = threadIdx.x, wid = tid >> 5, lane = tid & 31;
    const int wm = (wid >> 2) * 64;
    const int wn = (wid & 3) * 32;

    const __nv_bfloat16* Bh = g_Wthi + (size_t)which * NP * INF;
    const __nv_bfloat16* Bl = g_Wtlo + (size_t)which * NP * INF;

    float acc[4][4][4];
#pragma unroll
    for (int mi = 0; mi < 4; mi++)
#pragma unroll
        for (int nj = 0; nj < 4; nj++)
#pragma unroll
            for (int e = 0; e < 4; e++) acc[mi][nj][e] = 0.f;

    auto load_chunk = [&](int c, int stage) {
        uint32_t base = sb + stage * Q2ST;
        const int k0 = c * 32;
#pragma unroll
        for (int i = 0; i < 2; i++) {
            int idx = i * 256 + tid;
            int row = idx >> 2, v = idx & 3;
            uint32_t so = (uint32_t)(row * STR2 + v * 8) * 2;
            size_t gA = (size_t)(m0 + row) * INF + k0 + v * 8;
            size_t gB = (size_t)(n0 + row) * INF + k0 + v * 8;
            CP_A16(base + Q2_AH + so, g_Ahi + gA);
            CP_A16(base + Q2_AL + so, g_Alo + gA);
            CP_A16(base + Q2_BH + so, Bh + gB);
            CP_A16(base + Q2_BL + so, Bl + gB);
        }
        CP_COMMIT();
    };

    load_chunk(0, 0);

    for (int c = 0; c < 32; ++c) {
        const int s = c & 1;
        CP_WAIT0();
        __syncthreads();
        if (c < 31) load_chunk(c + 1, s ^ 1);

        uint32_t base = sb + s * Q2ST;
#pragma unroll
        for (int ki = 0; ki < 2; ki++) {
            uint32_t bh[2][4], bl[2][4];
#pragma unroll
            for (int p = 0; p < 2; p++) {
                ldsm4(bh[p], addrB_s(base + Q2_BH, wn + p * 16, ki * 16, lane, STR2));
                ldsm4(bl[p], addrB_s(base + Q2_BL, wn + p * 16, ki * 16, lane, STR2));
            }
#pragma unroll
            for (int mi = 0; mi < 4; mi++) {
                uint32_t ah[4], al[4];
                ldsm4(ah, addrA_s(base + Q2_AH, wm + mi * 16, ki * 16, lane, STR2));
                ldsm4(al, addrA_s(base + Q2_AL, wm + mi * 16, ki * 16, lane, STR2));
#pragma unroll
                for (int nj = 0; nj < 4; nj++) {
                    const uint32_t* bhp = &bh[nj >> 1][(nj & 1) * 2];
                    const uint32_t* blp = &bl[nj >> 1][(nj & 1) * 2];
                    mma16816(acc[mi][nj], ah, bhp, acc[mi][nj]);
                    mma16816(acc[mi][nj], al, bhp, acc[mi][nj]);
                    mma16816(acc[mi][nj], ah, blp, acc[mi][nj]);
                }
            }
        }
    }

    if (which == 0) {
        // Q: fp16 hi/lo
#pragma unroll
        for (int mi = 0; mi < 4; mi++) {
#pragma unroll
            for (int nj = 0; nj < 4; nj++) {
                int row = m0 + wm + mi * 16 + (lane >> 2);
                int col = n0 + wn + nj * 8 + 2 * (lane & 3);
                __half h0, l0, h1, l1;
                splith(acc[mi][nj][0], h0, l0); splith(acc[mi][nj][1], h1, l1);
                *(uint32_t*)&g_Qh[(size_t)row * NP + col] = pack2h(h0, h1);
                *(uint32_t*)&g_Ql[(size_t)row * NP + col] = pack2h(l0, l1);
                splith(acc[mi][nj][2], h0, l0); splith(acc[mi][nj][3], h1, l1);
                *(uint32_t*)&g_Qh[(size_t)(row + 8) * NP + col] = pack2h(h0, h1);
                *(uint32_t*)&g_Ql[(size_t)(row + 8) * NP + col] = pack2h(l0, l1);
            }
        }
    } else {
        // K: fp16 single
#pragma unroll
        for (int mi = 0; mi < 4; mi++) {
#pragma unroll
            for (int nj = 0; nj < 4; nj++) {
                int row = m0 + wm + mi * 16 + (lane >> 2);
                int col = n0 + wn + nj * 8 + 2 * (lane & 3);
                *(uint32_t*)&g_Kf[(size_t)row * NP + col]       = packh2(acc[mi][nj][0], acc[mi][nj][1]);
                *(uint32_t*)&g_Kf[(size_t)(row + 8) * NP + col] = packh2(acc[mi][nj][2], acc[mi][nj][3]);
            }
        }
    }
}

// ---------------------------------------------------------------------------
// Kernel 1b: V projection, single fp16 (1 MMA per tile). K chunks of 64.
// ---------------------------------------------------------------------------
#define V_A 0
#define V_B 18432
#define VST 36864
#define V_SMEM (2*VST)             // 73728

__global__ __launch_bounds__(256, 2) void vproj_mma() {
    extern __shared__ char sm[];
    uint32_t sb = smem_u32(sm);
    const int m0 = blockIdx.y * 128;
    const int n0 = blockIdx.x * 128;
    const int tid = threadIdx.x, wid = tid >> 5, lane = tid & 31;
    const int wm = (wid >> 2) * 64;
    const int wn = (wid & 3) * 32;

    float acc[4][4][4];
#pragma unroll
    for (int mi = 0; mi < 4; mi++)
#pragma unroll
        for (int nj = 0; nj < 4; nj++)
#pragma unroll
            for (int e = 0; e < 4; e++) acc[mi][nj][e] = 0.f;

    auto load_chunk = [&](int c, int stage) {
        uint32_t base = sb + stage * VST;
        const int k0 = c * 64;
#pragma unroll
        for (int i = 0; i < 4; i++) {
            int idx = i * 256 + tid;
            int row = idx >> 3, v = idx & 7;
            uint32_t so = (uint32_t)(row * STR + v * 8) * 2;
            CP_A16(base + V_A + so, g_Af  + (size_t)(m0 + row) * INF + k0 + v * 8);
            CP_A16(base + V_B + so, g_Wvf + (size_t)(n0 + row) * INF + k0 + v * 8);
        }
        CP_COMMIT();
    };

    load_chunk(0, 0);

    for (int c = 0; c < 16; ++c) {
        const int s = c & 1;
        CP_WAIT0();
        __syncthreads();
        if (c < 15) load_chunk(c + 1, s ^ 1);

        uint32_t base = sb + s * VST;
#pragma unroll
        for (int ki = 0; ki < 4; ki++) {
            uint32_t bq[2][4];
#pragma unroll
            for (int p = 0; p < 2; p++)
                ldsm4(bq[p], addrB_s(base + V_B, wn + p * 16, ki * 16, lane, STR));
#pragma unroll
            for (int mi = 0; mi < 4; mi++) {
                uint32_t aq[4];
                ldsm4(aq, addrA_s(base + V_A, wm + mi * 16, ki * 16, lane, STR));
#pragma unroll
                for (int nj = 0; nj < 4; nj++)
                    mma16816h(acc[mi][nj], aq, &bq[nj >> 1][(nj & 1) * 2], acc[mi][nj]);
            }
        }
    }

#pragma unroll
    for (int mi = 0; mi < 4; mi++) {
#pragma unroll
        for (int nj = 0; nj < 4; nj++) {
            int row = m0 + wm + mi * 16 + (lane >> 2);
            int col = n0 + wn + nj * 8 + 2 * (lane & 3);
            *(uint32_t*)&g_Vf[(size_t)row * NP + col]       = packh2(acc[mi][nj][0], acc[mi][nj][1]);
            *(uint32_t*)&g_Vf[(size_t)(row + 8) * NP + col] = packh2(acc[mi][nj][2], acc[mi][nj][3]);
        }
    }
}

// ---------------------------------------------------------------------------
// Kernel 2: FA2 flash attention. 128 q-rows, 256 threads, KV chunks 64,
// double-buffered. QK: 2 fp16 MMAs (Q hi/lo x K single). PV: 1 fp16 MMA.
// ---------------------------------------------------------------------------
#define AQ_H 0
#define AQ_L 18432
#define A_KV0 36864
#define A_KF 0
#define A_VF 9216
#define AST  18432                  // stage stride (K fp16 + V fp16)
#define AT_SMEM (A_KV0 + 2*AST)     // 73728

__global__ __launch_bounds__(256, 2) void attn_fa2() {
    extern __shared__ char sm[];
    uint32_t sb = smem_u32(sm);
    const int bh = blockIdx.y;
    const int b = bh >> 3, h = bh & 7;
    const size_t hoff = ((size_t)b * SEQ + (size_t)h * 256) * NP;
    const __half* Qh = g_Qh + hoff;
    const __half* Ql = g_Ql + hoff;
    const __half* Kf = g_Kf + hoff;
    const __half* Vf = g_Vf + hoff;

    const int q0 = blockIdx.x * 128;
    const int tid = threadIdx.x, wid = tid >> 5, lane = tid & 31;

    auto load_kv = [&](int kt, int stage) {
        uint32_t base = sb + A_KV0 + stage * AST;
        {
            int idx = tid;                 // 256 threads cover 2 mats x 64 rows x 8 v4 / 2
#pragma unroll
            for (int i = 0; i < 2; i++) {
                int id2 = i * 256 + idx;
                int row = id2 >> 3, v = id2 & 7;
                uint32_t so = (uint32_t)(row * STR + v * 8) * 2;
                size_t g = (size_t)(kt * 64 + row) * DPH + v * 8;
                CP_A16(base + A_KF + so, Kf + g);
                CP_A16(base + A_VF + so, Vf + g);
            }
        }
        CP_COMMIT();
    };

    // Persistent Q region (fp16 hi + lo)
#pragma unroll
    for (int i = 0; i < 4; i++) {
        int idx = i * 256 + tid;
        int row = idx >> 3, v = idx & 7;
        uint32_t so = (uint32_t)(row * STR + v * 8) * 2;
        size_t g = (size_t)(q0 + row) * DPH + v * 8;
        *(uint4*)(sm + AQ_H + so) = *(const uint4*)(Qh + g);
        *(uint4*)(sm + AQ_L + so) = *(const uint4*)(Ql + g);
    }
    load_kv(0, 0);
    __syncthreads();

    uint32_t aqh[4][4];
#pragma unroll
    for (int ki = 0; ki < 4; ki++)
        ldsm4(aqh[ki], addrA_s(sb + AQ_H, wid * 16, ki * 16, lane, STR));

    float cacc[8][4];
#pragma unroll
    for (int nj = 0; nj < 8; nj++)
#pragma unroll
        for (int e = 0; e < 4; e++) cacc[nj][e] = 0.f;
    float m0 = -1e30f, m1 = -1e30f, l0 = 0.f, l1 = 0.f;

    for (int kt = 0; kt < 32; kt++) {
        const int s = kt & 1;
        CP_WAIT0();
        __syncthreads();
        if (kt < 31) load_kv(kt + 1, s ^ 1);

        uint32_t base = sb + A_KV0 + s * AST;

        // S = Q @ K^T (2 fp16 MMAs per tile: qh*k + ql*k)
        float sacc[8][4];
#pragma unroll
        for (int nj = 0; nj < 8; nj++)
#pragma unroll
            for (int e = 0; e < 4; e++) sacc[nj][e] = 0.f;
#pragma unroll
        for (int ki = 0; ki < 4; ki++) {
            uint32_t aql[4];
            ldsm4(aql, addrA_s(sb + AQ_L, wid * 16, ki * 16, lane, STR));
#pragma unroll
            for (int p = 0; p < 4; p++) {
                uint32_t kf2[4];
                ldsm4(kf2, addrB_s(base + A_KF, p * 16, ki * 16, lane, STR));
#pragma unroll
                for (int q = 0; q < 2; q++) {
                    int nj = 2 * p + q;
                    mma16816h(sacc[nj], aqh[ki], &kf2[q * 2], sacc[nj]);
                    mma16816h(sacc[nj], aql,     &kf2[q * 2], sacc[nj]);
                }
            }
        }

        // register softmax: rows r=lane>>2 (m0/l0) and r+8 (m1/l1)
        float mx0 = -1e30f, mx1 = -1e30f;
#pragma unroll
        for (int nj = 0; nj < 8; nj++) {
            mx0 = fmaxf(mx0, fmaxf(sacc[nj][0], sacc[nj][1]));
            mx1 = fmaxf(mx1, fmaxf(sacc[nj][2], sacc[nj][3]));
        }
        mx0 = fmaxf(mx0, __shfl_xor_sync(0xffffffffu, mx0, 1));
        mx0 = fmaxf(mx0, __shfl_xor_sync(0xffffffffu, mx0, 2));
        mx1 = fmaxf(mx1, __shfl_xor_sync(0xffffffffu, mx1, 1));
        mx1 = fmaxf(mx1, __shfl_xor_sync(0xffffffffu, mx1, 2));
        float mn0 = fmaxf(m0, mx0), mn1 = fmaxf(m1, mx1);
        float c0 = __expf(m0 - mn0), c1 = __expf(m1 - mn1);
        m0 = mn0; m1 = mn1;

        uint32_t aP[4][4];
        float ls0 = 0.f, ls1 = 0.f;
#pragma unroll
        for (int ki = 0; ki < 4; ki++) {
#pragma unroll
            for (int jj = 0; jj < 2; jj++) {
                int nj = 2 * ki + jj;
                float p0 = __expf(sacc[nj][0] - mn0);
                float p1 = __expf(sacc[nj][1] - mn0);
                float p2 = __expf(sacc[nj][2] - mn1);
                float p3 = __expf(sacc[nj][3] - mn1);
                ls0 += p0 + p1; ls1 += p2 + p3;
                aP[ki][2 * jj + 0] = packh2(p0, p1);
                aP[ki][2 * jj + 1] = packh2(p2, p3);
            }
        }
        ls0 += __shfl_xor_sync(0xffffffffu, ls0, 1);
        ls0 += __shfl_xor_sync(0xffffffffu, ls0, 2);
        ls1 += __shfl_xor_sync(0xffffffffu, ls1, 1);
        ls1 += __shfl_xor_sync(0xffffffffu, ls1, 2);
        l0 = l0 * c0 + ls0;
        l1 = l1 * c1 + ls1;

#pragma unroll
        for (int nj = 0; nj < 8; nj++) {
            cacc[nj][0] *= c0; cacc[nj][1] *= c0;
            cacc[nj][2] *= c1; cacc[nj][3] *= c1;
        }

        // PV: single fp16 MMA per tile
#pragma unroll
        for (int ki = 0; ki < 4; ki++) {
#pragma unroll
            for (int p = 0; p < 4; p++) {
                uint32_t v2[4];
                ldsm4t(v2, addrV_s(base + A_VF, ki * 16, p * 16, lane, STR));
#pragma unroll
                for (int q = 0; q < 2; q++) {
                    int nj = 2 * p + q;
                    mma16816h(cacc[nj], aP[ki], &v2[q * 2], cacc[nj]);
                }
            }
        }
    }

    float inv0 = 1.0f / (8.0f * l0);   // post-softmax /sqrt(d) quirk
    float inv1 = 1.0f / (8.0f * l1);
    {
        int r = wid * 16 + (lane >> 2);
        size_t grow = (size_t)bh * SEQ + q0 + r;
#pragma unroll
        for (int nj = 0; nj < 8; nj++) {
            int col = nj * 8 + 2 * (lane & 3);
            *(uint32_t*)&g_Cf[grow * DPH + col]       = packh2(cacc[nj][0] * inv0, cacc[nj][1] * inv0);
            *(uint32_t*)&g_Cf[(grow + 8) * DPH + col] = packh2(cacc[nj][2] * inv1, cacc[nj][3] * inv1);
        }
    }
}

// ---------------------------------------------------------------------------
// Kernel 3: output projection, single fp16: ctx[32768,64] @ Wo[64,1024] + bo
// ---------------------------------------------------------------------------
#define O_A 0
#define O_B 18432
#define O_SMEM 36864

__global__ __launch_bounds__(256, 2) void outproj_mma(const float* __restrict__ bo,
                                                      float* __restrict__ out) {
    extern __shared__ char sm[];
    uint32_t sb = smem_u32(sm);
    const int m0 = blockIdx.y * 128;
    const int n0 = blockIdx.x * 128;
    const int tid = threadIdx.x, wid = tid >> 5, lane = tid & 31;
    const int wm = (wid >> 2) * 64;
    const int wn = (wid & 3) * 32;

#pragma unroll
    for (int i = 0; i < 4; i++) {
        int idx = i * 256 + tid;
        int row = idx >> 3, v = idx & 7;
        uint32_t so = (uint32_t)(row * STR + v * 8) * 2;
        CP_A16(sb + O_A + so, g_Cf  + (size_t)(m0 + row) * DPH + v * 8);
        CP_A16(sb + O_B + so, g_Wof + (size_t)(n0 + row) * DPH + v * 8);
    }
    CP_COMMIT();
    CP_WAIT0();
    __syncthreads();

    float acc[4][4][4];
#pragma unroll
    for (int mi = 0; mi < 4; mi++)
#pragma unroll
        for (int nj = 0; nj < 4; nj++)
#pragma unroll
            for (int e = 0; e < 4; e++) acc[mi][nj][e] = 0.f;

#pragma unroll
    for (int ki = 0; ki < 4; ki++) {
        uint32_t bq[2][4];
#pragma unroll
        for (int p = 0; p < 2; p++)
            ldsm4(bq[p], addrB_s(sb + O_B, wn + p * 16, ki * 16, lane, STR));
#pragma unroll
        for (int mi = 0; mi < 4; mi++) {
            uint32_t aq[4];
            ldsm4(aq, addrA_s(sb + O_A, wm + mi * 16, ki * 16, lane, STR));
#pragma unroll
            for (int nj = 0; nj < 4; nj++)
                mma16816h(acc[mi][nj], aq, &bq[nj >> 1][(nj & 1) * 2], acc[mi][nj]);
        }
    }

#pragma unroll
    for (int mi = 0; mi < 4; mi++) {
#pragma unroll
        for (int nj = 0; nj < 4; nj++) {
            int row = m0 + wm + mi * 16 + (lane >> 2);
            int col = n0 + wn + nj * 8 + 2 * (lane & 3);
            float2 bv = *(const float2*)&bo[col];
            *(float2*)&out[(size_t)row * OUTF + col] =
                make_float2(acc[mi][nj][0] + bv.x, acc[mi][nj][1] + bv.y);
            *(float2*)&out[(size_t)(row + 8) * OUTF + col] =
                make_float2(acc[mi][nj][2] + bv.x, acc[mi][nj][3] + bv.y);
        }
    }
}

// ---------------------------------------------------------------------------
extern "C" void kernel_launch(void* const* d_in, const int* in_sizes, int n_in,
                              void* d_out, int out_size)
{
    const float* inputs = (const float*)d_in[0];
    const float* Wq     = (const float*)d_in[1];
    const float* Wk     = (const float*)d_in[2];
    const float* Wv     = (const float*)d_in[3];
    const float* Wo     = (const float*)d_in[4];
    const float* bo     = (const float*)d_in[5];
    float* out = (float*)d_out;

    cudaFuncSetAttribute(qk_mma, cudaFuncAttributeMaxDynamicSharedMemorySize, QG_SMEM);
    cudaFuncSetAttribute(vproj_mma, cudaFuncAttributeMaxDynamicSharedMemorySize, V_SMEM);
    cudaFuncSetAttribute(attn_fa2, cudaFuncAttributeMaxDynamicSharedMemorySize, AT_SMEM);
    cudaFuncSetAttribute(outproj_mma, cudaFuncAttributeMaxDynamicSharedMemorySize, O_SMEM);

    prep_split_A<<<(MROWS * INF / 4) / 256, 256>>>(inputs);
    {
        dim3 grid(INF / 32, NP / 32, 3);
        prep_Wt<<<grid, dim3(32, 8)>>>(Wq, Wk, Wv);
    }
    {
        dim3 grid(DPH / 32, OUTF / 32);
        prep_Wo<<<grid, dim3(32, 8)>>>(Wo);
    }
    {
        dim3 grid(NP / 128, MROWS / 128, 2);
        qk_mma<<<grid, 256, QG_SMEM>>>();
    }
    {
        dim3 grid(NP / 128, MROWS / 128);
        vproj_mma<<<grid, 256, V_SMEM>>>();
    }
    {
        dim3 grid(SEQ / 128, BATCH * HEADS);
        attn_fa2<<<grid, 256, AT_SMEM>>>();
    }
    {
        dim3 grid(OUTF / 128, CTXROWS / 128);
        outproj_mma<<<grid, 256, O_SMEM>>>(bo, out);
    }
}